// round 7
// baseline (speedup 1.0000x reference)
#include <cuda_runtime.h>
#include <cuda_fp16.h>
#include <stdint.h>

#define FF 32
#define HH 160
#define BB 64
#define TT 256
#define TM 64
#define NTH 256
#define EAS 168      /* half stride for A images */
#define XSTR 33      /* x tile row stride (floats) */
#define SCS 164      /* scratch row stride (floats) */

__device__ float g_weights[BB * FF];
/* B fragments: [t(35)][kt(10)][nt(20)][lane(32)] -> uint2 {b0,b1} */
__device__ __align__(16) uint2 g_Bfrag[35 * 6400];
/* per-f parameter pack: [f][ W1|b1|b2|Wg|bg|lng|lnb ][160] */
__device__ __align__(16) float g_Par[FF * 1120];

/* ------------------------------ helpers ---------------------------------- */
__device__ __forceinline__ uint32_t smem_u32(const void* p) {
    uint32_t a;
    asm("{ .reg .u64 t; cvta.to.shared.u64 t, %1; cvt.u32.u64 %0, t; }" : "=r"(a) : "l"(p));
    return a;
}
__device__ __forceinline__ uint32_t pack_h2(float a, float b) {
    __half2 h = __floats2half2_rn(a, b);
    return *reinterpret_cast<uint32_t*>(&h);
}
__device__ __forceinline__ float fsigmoid(float z) {
    float z2 = z * z;
    float t = fmaf(z2, 2.0833333e-3f, -2.0833334e-2f);
    t = fmaf(z2, t, 0.25f);
    return fmaf(z, t, 0.5f);
}
__device__ __forceinline__ float felu(float z) {
    float p = fmaf(z, 8.3333333e-3f, 4.1666667e-2f);
    p = fmaf(z, p, 1.6666667e-1f);
    p = fmaf(z, p, 0.5f);
    p = fmaf(z, p, 1.0f);
    p = z * p;
    return z > 0.f ? z : p;
}
__device__ __forceinline__ void mma16816(float* c, uint32_t a0, uint32_t a1,
                                         uint32_t a2, uint32_t a3,
                                         uint32_t b0, uint32_t b1) {
    asm volatile(
        "mma.sync.aligned.m16n8k16.row.col.f32.f16.f16.f32 "
        "{%0,%1,%2,%3}, {%4,%5,%6,%7}, {%8,%9}, {%0,%1,%2,%3};"
        : "+f"(c[0]), "+f"(c[1]), "+f"(c[2]), "+f"(c[3])
        : "r"(a0), "r"(a1), "r"(a2), "r"(a3), "r"(b0), "r"(b1));
}
__device__ __forceinline__ void cp_async16(uint32_t saddr, const void* gptr) {
    asm volatile("cp.async.cg.shared.global [%0], [%1], 16;" :: "r"(saddr), "l"(gptr));
}
#define LDMX4(a0, a1, a2, a3, p)                                                 \
    asm volatile("ldmatrix.sync.aligned.m8n8.x4.shared.b16 {%0,%1,%2,%3}, [%4];" \
                 : "=r"(a0), "=r"(a1), "=r"(a2), "=r"(a3) : "r"(p))

/* phase-1 chunk: 5 k-tiles, 2 m-tiles per warp, B from smem stage.
   acc layout: acc[(j*2+t)*4 + c], t = m-tile (0/1), j = n-tile (0..4). */
__device__ __forceinline__ void gemm_chunk(float* acc, uint32_t ap0, uint32_t ap1,
                                           int h, const uint2* sb) {
#pragma unroll
    for (int kt = 0; kt < 5; ++kt) {
        uint32_t a0, a1, a2, a3, c0, c1, c2, c3;
        LDMX4(a0, a1, a2, a3, ap0 + (h * 5 + kt) * 32);
        LDMX4(c0, c1, c2, c3, ap1 + (h * 5 + kt) * 32);
#pragma unroll
        for (int j = 0; j < 5; ++j) {
            uint2 bv = sb[(kt * 20 + j) * 32];
            mma16816(acc + (j * 2 + 0) * 4, a0, a1, a2, a3, bv.x, bv.y);
            mma16816(acc + (j * 2 + 1) * 4, c0, c1, c2, c3, bv.x, bv.y);
        }
    }
}
/* phase-2 gemm: full K=160, B from global */
__device__ __forceinline__ void gemm160_g(float* acc, uint32_t ap0, uint32_t ap1,
                                          const uint2* bp) {
#pragma unroll
    for (int kt = 0; kt < 10; ++kt) {
        uint32_t a0, a1, a2, a3, c0, c1, c2, c3;
        LDMX4(a0, a1, a2, a3, ap0 + kt * 32);
        LDMX4(c0, c1, c2, c3, ap1 + kt * 32);
#pragma unroll
        for (int j = 0; j < 5; ++j) {
            uint2 bv = bp[(kt * 20 + j) * 32];
            mma16816(acc + (j * 2 + 0) * 4, a0, a1, a2, a3, bv.x, bv.y);
            mma16816(acc + (j * 2 + 1) * 4, c0, c1, c2, c3, bv.x, bv.y);
        }
    }
}

/* --------------- kernel 0: merged prep (B fragments + params) + weights --- */
__global__ void pre_kernel(const float* __restrict__ W2,
                           const float* __restrict__ oW1,
                           const float* __restrict__ oW2,
                           const float* __restrict__ oWg,
                           const float* __restrict__ W1,
                           const float* __restrict__ b1,
                           const float* __restrict__ b2,
                           const float* __restrict__ Wg,
                           const float* __restrict__ bg,
                           const float* __restrict__ lng,
                           const float* __restrict__ lnb,
                           const float* __restrict__ x,
                           const float* __restrict__ Ww,
                           const float* __restrict__ bw,
                           float* __restrict__ out_tail) {
    if (blockIdx.x >= BB) {
        int t = blockIdx.x - BB; /* 0..34 */
        const float* src = (t < 32) ? (W2 + (size_t)t * HH * HH)
                                    : (t == 32 ? oW1 : (t == 33 ? oW2 : oWg));
        for (int idx = threadIdx.x; idx < 6400; idx += blockDim.x) {
            int kt = idx / 640;
            int nt = (idx / 32) % 20;
            int l  = idx & 31;
            int k0 = kt * 16 + (l & 3) * 2;
            int n  = nt * 8 + (l >> 2);
            uint2 v;
            v.x = pack_h2(src[k0 * HH + n],       src[(k0 + 1) * HH + n]);
            v.y = pack_h2(src[(k0 + 8) * HH + n], src[(k0 + 9) * HH + n]);
            g_Bfrag[(size_t)t * 6400 + idx] = v;
        }
        if (t < FF) {
            const float* srcs[7] = { W1 + t * HH, b1 + t * HH, b2 + t * HH,
                                     Wg + t * HH, bg + t * HH,
                                     lng + t * HH, lnb + t * HH };
            for (int j = threadIdx.x; j < 1120; j += blockDim.x)
                g_Par[t * 1120 + j] = srcs[j / 160][j % 160];
        }
        return;
    }
    int b = blockIdx.x;
    int tid = threadIdx.x;
    int c = tid & 31, g = tid >> 5;
    const float* xb = x + b * (TT * FF);
    float acc = 0.f;
#pragma unroll 4
    for (int r = g; r < TT * FF; r += 8) acc = fmaf(xb[r], Ww[r * FF + c], acc);
    __shared__ float red[8][32];
    red[g][c] = acc;
    __syncthreads();
    if (tid < 32) {
        float s = 0.f;
#pragma unroll
        for (int i = 0; i < 8; ++i) s += red[i][tid];
        s += bw[tid];
        float m = s;
#pragma unroll
        for (int o = 16; o; o >>= 1) m = fmaxf(m, __shfl_xor_sync(0xffffffffu, m, o));
        float e = expf(s - m);
        float se = e;
#pragma unroll
        for (int o = 16; o; o >>= 1) se += __shfl_xor_sync(0xffffffffu, se, o);
        float w = e / se;
        g_weights[b * 32 + tid] = w;
        out_tail[b * 32 + tid] = w;
    }
}

/* ------------------------- kernel 1: fused VSN (HMMA) ---------------------
   SMEM (bytes):
     xs      [0,       8448)   64 x 33 fp32
     eaA     [8448,    29952)  64 x 168 fp16
     red     [29952,   32000)  64 x 8 fp32
     mred    [32000,   32512)  64 x 2 fp32
     pbuf    [32512,   41472)  2 x 4480 param pack
     Bstage  [41472,   92672)  2 x 25600 cp.async double buffer (phase 1)
     eaB     [41472,   62976)  64 x 168 fp16  (phase 2, aliases Bstage)
     scratch [62976,  104960)  64 x 164 fp32  (phase 2, aliases Bstage)       */
#define OFF_EAA  8448
#define OFF_RED  29952
#define OFF_MRED 32000
#define OFF_PBUF 32512
#define PBN      4480
#define OFF_BST  41472
#define CHKB     25600
#define OFF_EAB  41472
#define OFF_SCR  62976
#define SMEM_TOTAL 104960

__global__ void __launch_bounds__(NTH, 2)
fused_mma(const float* __restrict__ x,
          const float* __restrict__ ob1, const float* __restrict__ ob2,
          const float* __restrict__ obg,
          const float* __restrict__ olng, const float* __restrict__ olnb,
          float* __restrict__ out) {
    extern __shared__ char smem[];
    float*  xs      = (float*)smem;
    __half* eaA     = (__half*)(smem + OFF_EAA);
    float*  red     = (float*)(smem + OFF_RED);
    float*  mred    = (float*)(smem + OFF_MRED);
    __half* eaB     = (__half*)(smem + OFF_EAB);
    float*  scratch = (float*)(smem + OFF_SCR);
    const uint32_t sbase = smem_u32(smem);

    const int tid = threadIdx.x;
    const int l = tid & 31, wid = tid >> 5;
    const int mg = wid >> 2, nhq = wid & 3;      /* 2 row-groups x 4 col-groups */
    const int rA = mg * 32 + (l >> 2);
    int rr[4];
    rr[0] = rA; rr[1] = rA + 8; rr[2] = rA + 16; rr[3] = rA + 24;
    const int colbq = nhq * 40;
    const int colt = (l & 3) * 2;
    const int m0 = blockIdx.x * TM;
    const int bb = blockIdx.x >> 2;

    /* ldmatrix lane pointers for the warp's two m-tiles */
    const int lrow = mg * 32 + (l & 15);
    const int lcol = (l >> 4) * 8;
    const uint32_t aAp0 = sbase + OFF_EAA + (lrow * EAS + lcol) * 2;
    const uint32_t aAp1 = aAp0 + 16 * EAS * 2;
    const uint32_t aBp0 = sbase + OFF_EAB + (lrow * EAS + lcol) * 2;
    const uint32_t aBp1 = aBp0 + 16 * EAS * 2;
    const int sboff = nhq * 160 + l;             /* uint2 elements */

    const int grow = tid >> 2;
    const int gcb = (tid & 3) * 40;

    {
        const float4* xsrc = (const float4*)(x + (size_t)m0 * FF);
        for (int i = tid; i < TM * FF / 4; i += NTH) {
            float4 v = xsrc[i];
            float* d = xs + (i >> 3) * XSTR + ((i & 7) << 2);
            d[0] = v.x; d[1] = v.y; d[2] = v.z; d[3] = v.w;
        }
    }
    /* preload B chunk 0 + params f=0 */
    {
        const uint4* gsrc = (const uint4*)g_Bfrag;
        for (int j = tid; j < 1600; j += NTH)
            cp_async16(sbase + OFF_BST + j * 16, gsrc + j);
        const float4* psrc = (const float4*)g_Par;
        for (int j = tid; j < 280; j += NTH)
            cp_async16(sbase + OFF_PBUF + j * 16, psrc + j);
        asm volatile("cp.async.commit_group;" ::: "memory");
    }
    float comb[40];
#pragma unroll
    for (int i = 0; i < 40; ++i) comb[i] = 0.f;
    asm volatile("cp.async.wait_group 0;" ::: "memory");
    __syncthreads();

    float acc[40];

    /* ========================= phase 1: f loop ============================ */
    for (int f = 0; f < FF; ++f) {
        const float* pb = (const float*)(smem + OFF_PBUF + (f & 1) * PBN);

        /* A = elu(x[.,f]*W1[f,:]+b1[f,:]) -> eaA (params from smem) */
        {
            const float xvg = xs[grow * XSTR + f];
            const float4* W1f = (const float4*)(pb + gcb);
            const float4* b1f = (const float4*)(pb + 160 + gcb);
            uint4* eg = (uint4*)(eaA + grow * EAS + gcb);
#pragma unroll
            for (int q = 0; q < 5; ++q) {
                float4 w0 = W1f[2 * q],     bb0 = b1f[2 * q];
                float4 w1 = W1f[2 * q + 1], bb1 = b1f[2 * q + 1];
                uint4 o;
                o.x = pack_h2(felu(fmaf(xvg, w0.x, bb0.x)), felu(fmaf(xvg, w0.y, bb0.y)));
                o.y = pack_h2(felu(fmaf(xvg, w0.z, bb0.z)), felu(fmaf(xvg, w0.w, bb0.w)));
                o.z = pack_h2(felu(fmaf(xvg, w1.x, bb1.x)), felu(fmaf(xvg, w1.y, bb1.y)));
                o.w = pack_h2(felu(fmaf(xvg, w1.z, bb1.z)), felu(fmaf(xvg, w1.w, bb1.w)));
                eg[q] = o;
            }
        }

#pragma unroll
        for (int i = 0; i < 40; ++i) acc[i] = 0.f;

#pragma unroll
        for (int h = 0; h < 2; ++h) {
            const int c = f * 2 + h;
            asm volatile("cp.async.wait_group 0;" ::: "memory");
            __syncthreads();
            if (c + 1 < 64) {
                const uint4* gsrc = (const uint4*)g_Bfrag + (size_t)(c + 1) * 1600;
                const uint32_t dst = sbase + OFF_BST + ((c + 1) & 1) * CHKB;
                for (int j = tid; j < 1600; j += NTH)
                    cp_async16(dst + j * 16, gsrc + j);
                if (h == 0 && f + 1 < FF) {
                    const float4* psrc = (const float4*)(g_Par + (size_t)(f + 1) * 1120);
                    const uint32_t pdst = sbase + OFF_PBUF + ((f + 1) & 1) * PBN;
                    for (int j = tid; j < 280; j += NTH)
                        cp_async16(pdst + j * 16, psrc + j);
                }
                asm volatile("cp.async.commit_group;" ::: "memory");
            }
            const uint2* sb = (const uint2*)(smem + OFF_BST + (c & 1) * CHKB) + sboff;
            gemm_chunk(acc, aAp0, aAp1, h, sb);
        }

        /* epilogue: 4 rows x 10 cols per thread */
        float xvv[4], c0v[4], s1v[4], s2v[4];
#pragma unroll
        for (int ri = 0; ri < 4; ++ri) {
            xvv[ri] = xs[rr[ri] * XSTR + f];
            c0v[ri] = 0.5f * xvv[ri];
            s1v[ri] = 0.f; s2v[ri] = 0.f;
        }
        const float* b2f = pb + 320;
        const float* Wgf = pb + 480;
        const float* bgf = pb + 640;
#pragma unroll
        for (int j = 0; j < 5; ++j) {
            int col = colbq + j * 8 + colt;
            float2 vb2 = *(const float2*)(b2f + col);
            float2 vwg = *(const float2*)(Wgf + col);
            float2 vbg = *(const float2*)(bgf + col);
#pragma unroll
            for (int ri = 0; ri < 4; ++ri) {
                int idx = (j * 2 + (ri >> 1)) * 4 + (ri & 1) * 2;
                float xv = xvv[ri];
                float a2 = acc[idx] + vb2.x;
                float gv = fsigmoid(fmaf(xv, vwg.x, vbg.x));
                float ft = fmaf(gv, a2 - xv, xv);
                acc[idx] = ft;
                float d = ft - c0v[ri]; s1v[ri] += d; s2v[ri] = fmaf(d, d, s2v[ri]);
                a2 = acc[idx + 1] + vb2.y;
                gv = fsigmoid(fmaf(xv, vwg.y, vbg.y));
                ft = fmaf(gv, a2 - xv, xv);
                acc[idx + 1] = ft;
                d = ft - c0v[ri]; s1v[ri] += d; s2v[ri] = fmaf(d, d, s2v[ri]);
            }
        }
#pragma unroll
        for (int ri = 0; ri < 4; ++ri) {
#pragma unroll
            for (int o = 1; o < 4; o <<= 1) {
                s1v[ri] += __shfl_xor_sync(0xffffffffu, s1v[ri], o);
                s2v[ri] += __shfl_xor_sync(0xffffffffu, s2v[ri], o);
            }
        }
        if ((l & 3) == 0) {
#pragma unroll
            for (int ri = 0; ri < 4; ++ri)
                *(float2*)(red + rr[ri] * 8 + nhq * 2) = make_float2(s1v[ri], s2v[ri]);
        }
        __syncthreads();
        float invv[4], nmiv[4];
#pragma unroll
        for (int ri = 0; ri < 4; ++ri) {
            float4 qa = *(const float4*)(red + rr[ri] * 8);
            float4 qb = *(const float4*)(red + rr[ri] * 8 + 4);
            float S1 = (qa.x + qa.z) + (qb.x + qb.z);
            float S2 = (qa.y + qa.w) + (qb.y + qb.w);
            float dm = S1 * (1.f / 160.f);
            float var = fmaf(-dm, dm, S2 * (1.f / 160.f));
            invv[ri] = rsqrtf(var + 1e-3f);
            nmiv[ri] = -(c0v[ri] + dm) * invv[ri];
        }
        float wbf = g_weights[bb * FF + f];
        const float* lgf = pb + 800;
        const float* lbf = pb + 960;
#pragma unroll
        for (int j = 0; j < 5; ++j) {
            int col = colbq + j * 8 + colt;
            float2 vlg = *(const float2*)(lgf + col);
            float2 vlb = *(const float2*)(lbf + col);
#pragma unroll
            for (int ri = 0; ri < 4; ++ri) {
                int idx = (j * 2 + (ri >> 1)) * 4 + (ri & 1) * 2;
                float y = fmaf(fmaf(acc[idx], invv[ri], nmiv[ri]), vlg.x, vlb.x);
                comb[idx] = fmaf(wbf, y, comb[idx]);
                y = fmaf(fmaf(acc[idx + 1], invv[ri], nmiv[ri]), vlg.y, vlb.y);
                comb[idx + 1] = fmaf(wbf, y, comb[idx + 1]);
            }
        }
    }

    /* ========================= phase 2: output MLP ======================== */
    __syncthreads();
#pragma unroll
    for (int j = 0; j < 5; ++j) {
#pragma unroll
        for (int ri = 0; ri < 4; ++ri) {
            int idx = (j * 2 + (ri >> 1)) * 4 + (ri & 1) * 2;
            *(uint32_t*)(eaA + rr[ri] * EAS + colbq + j * 8 + colt) =
                pack_h2(comb[idx], comb[idx + 1]);
        }
    }
    __syncthreads();

    /* GEMM1: h1 = elu(comb @ oW1 + ob1) -> eaB */
#pragma unroll
    for (int i = 0; i < 40; ++i) acc[i] = 0.f;
    gemm160_g(acc, aAp0, aAp1, g_Bfrag + 32u * 6400 + sboff);
#pragma unroll
    for (int j = 0; j < 5; ++j) {
        int col = colbq + j * 8 + colt;
        float2 vb = *(const float2*)(ob1 + col);
#pragma unroll
        for (int ri = 0; ri < 4; ++ri) {
            int idx = (j * 2 + (ri >> 1)) * 4 + (ri & 1) * 2;
            *(uint32_t*)(eaB + rr[ri] * EAS + col) =
                pack_h2(felu(acc[idx] + vb.x), felu(acc[idx + 1] + vb.y));
        }
    }
    __syncthreads();

    /* GEMM2: oa = h1 @ oW2 + ob2 -> scratch */
#pragma unroll
    for (int i = 0; i < 40; ++i) acc[i] = 0.f;
    gemm160_g(acc, aBp0, aBp1, g_Bfrag + 33u * 6400 + sboff);
#pragma unroll
    for (int j = 0; j < 5; ++j) {
        int col = colbq + j * 8 + colt;
        float2 vb = *(const float2*)(ob2 + col);
#pragma unroll
        for (int ri = 0; ri < 4; ++ri) {
            int idx = (j * 2 + (ri >> 1)) * 4 + (ri & 1) * 2;
            *(float2*)(scratch + rr[ri] * SCS + col) =
                make_float2(acc[idx] + vb.x, acc[idx + 1] + vb.y);
        }
    }

    /* GEMM3: og = sigmoid(comb @ oWg + obg); v = og*(oa-comb)+comb */
#pragma unroll
    for (int i = 0; i < 40; ++i) acc[i] = 0.f;
    gemm160_g(acc, aAp0, aAp1, g_Bfrag + 34u * 6400 + sboff);
    {
        float s1v[4] = {0.f, 0.f, 0.f, 0.f};
        float s2v[4] = {0.f, 0.f, 0.f, 0.f};
#pragma unroll
        for (int j = 0; j < 5; ++j) {
            int col = colbq + j * 8 + colt;
            float2 vb = *(const float2*)(obg + col);
#pragma unroll
            for (int ri = 0; ri < 4; ++ri) {
                int idx = (j * 2 + (ri >> 1)) * 4 + (ri & 1) * 2;
                float2 oa = *(float2*)(scratch + rr[ri] * SCS + col);
                float og = fsigmoid(acc[idx] + vb.x);
                float c = comb[idx];
                float v = fmaf(og, oa.x - c, c);
                oa.x = v; s1v[ri] += v; s2v[ri] = fmaf(v, v, s2v[ri]);
                og = fsigmoid(acc[idx + 1] + vb.y);
                c = comb[idx + 1];
                v = fmaf(og, oa.y - c, c);
                oa.y = v; s1v[ri] += v; s2v[ri] = fmaf(v, v, s2v[ri]);
                *(float2*)(scratch + rr[ri] * SCS + col) = oa;
            }
        }
#pragma unroll
        for (int ri = 0; ri < 4; ++ri) {
#pragma unroll
            for (int o = 1; o < 4; o <<= 1) {
                s1v[ri] += __shfl_xor_sync(0xffffffffu, s1v[ri], o);
                s2v[ri] += __shfl_xor_sync(0xffffffffu, s2v[ri], o);
            }
        }
        if ((l & 3) == 0) {
#pragma unroll
            for (int ri = 0; ri < 4; ++ri)
                *(float2*)(red + rr[ri] * 8 + nhq * 2) = make_float2(s1v[ri], s2v[ri]);
        }
        __syncthreads();
        if ((l & 3) == 0 && nhq == 0) {
#pragma unroll
            for (int ri = 0; ri < 4; ++ri) {
                float4 qa = *(const float4*)(red + rr[ri] * 8);
                float4 qb = *(const float4*)(red + rr[ri] * 8 + 4);
                float S1 = (qa.x + qa.z) + (qb.x + qb.z);
                float S2 = (qa.y + qa.w) + (qb.y + qb.w);
                float mean = S1 * (1.f / 160.f);
                float var = fmaf(-mean, mean, S2 * (1.f / 160.f));
                *(float2*)(mred + rr[ri] * 2) = make_float2(mean, rsqrtf(var + 1e-3f));
            }
        }
        __syncthreads();
    }

    /* final LN + coalesced store */
    {
        const int row = tid >> 2;
        const int cb2 = (tid & 3) * 40;
        float2 mi = *(const float2*)(mred + row * 2);
        const float mean = mi.x, inv = mi.y;
        const float* sv = scratch + row * SCS + cb2;
        const float4* lg4 = (const float4*)(olng + cb2);
        const float4* lb4 = (const float4*)(olnb + cb2);
        float4* orow = (float4*)(out + (size_t)(m0 + row) * HH + cb2);
#pragma unroll
        for (int q = 0; q < 10; ++q) {
            float4 g4 = lg4[q], bq = lb4[q], o;
            o.x = fmaf((sv[q * 4 + 0] - mean) * inv, g4.x, bq.x);
            o.y = fmaf((sv[q * 4 + 1] - mean) * inv, g4.y, bq.y);
            o.z = fmaf((sv[q * 4 + 2] - mean) * inv, g4.z, bq.z);
            o.w = fmaf((sv[q * 4 + 3] - mean) * inv, g4.w, bq.w);
            orow[q] = o;
        }
    }
}

/* --------------------------------- launch --------------------------------- */
extern "C" void kernel_launch(void* const* d_in, const int* in_sizes, int n_in,
                              void* d_out, int out_size) {
    const float* x    = (const float*)d_in[0];
    const float* W1   = (const float*)d_in[1];
    const float* b1   = (const float*)d_in[2];
    const float* W2   = (const float*)d_in[3];
    const float* b2   = (const float*)d_in[4];
    const float* Wg   = (const float*)d_in[5];
    const float* bg   = (const float*)d_in[6];
    const float* lng  = (const float*)d_in[7];
    const float* lnb  = (const float*)d_in[8];
    const float* Ww   = (const float*)d_in[9];
    const float* bw   = (const float*)d_in[10];
    const float* oW1  = (const float*)d_in[11];
    const float* ob1  = (const float*)d_in[12];
    const float* oW2  = (const float*)d_in[13];
    const float* ob2  = (const float*)d_in[14];
    const float* oWg  = (const float*)d_in[15];
    const float* obg  = (const float*)d_in[16];
    const float* olng = (const float*)d_in[17];
    const float* olnb = (const float*)d_in[18];
    float* out = (float*)d_out;

    cudaFuncSetAttribute(fused_mma, cudaFuncAttributeMaxDynamicSharedMemorySize,
                         SMEM_TOTAL);

    pre_kernel<<<BB + 35, 256>>>(W2, oW1, oW2, oWg,
                                 W1, b1, b2, Wg, bg, lng, lnb,
                                 x, Ww, bw, out + (size_t)BB * TT * HH);
    fused_mma<<<(BB * TT) / TM, NTH, SMEM_TOTAL>>>(
        x, ob1, ob2, obg, olng, olnb, out);
}

// round 9
// speedup vs baseline: 1.0067x; 1.0067x over previous
#include <cuda_runtime.h>
#include <cuda_fp16.h>
#include <stdint.h>

#define FF 32
#define HH 160
#define BB 64
#define TT 256
#define TM 64
#define NTH 256
#define EAS 168      /* half stride for A images (>=160, ldmatrix-friendly) */
#define XSTR 33      /* x tile row stride (floats) */
#define SCS 164      /* scratch row stride (floats) */

__device__ float g_weights[BB * FF];
/* B fragments: [t(35)][kt(10)][nt(20)][lane(32)] -> uint2 {b0,b1} */
__device__ __align__(16) uint2 g_Bfrag[35 * 6400];
/* per-f parameter pack, 1280 floats per f:
   [0,160)=W1  [160,320)=b1  then 5 fragment-major arrays of 192 floats:
   b2@320, Wg@512, bg@704, lng@896, lnb@1088.
   fragment-major: pos = g*48 + tt*12 + j*2 + e for col = g*40 + j*8 + tt*2 + e */
__device__ __align__(16) float g_Par[FF * 1280];

/* ------------------------------ helpers ---------------------------------- */
__device__ __forceinline__ uint32_t smem_u32(const void* p) {
    uint32_t a;
    asm("{ .reg .u64 t; cvta.to.shared.u64 t, %1; cvt.u32.u64 %0, t; }" : "=r"(a) : "l"(p));
    return a;
}
__device__ __forceinline__ uint32_t pack_h2(float a, float b) {
    __half2 h = __floats2half2_rn(a, b);
    return *reinterpret_cast<uint32_t*>(&h);
}
__device__ __forceinline__ float fsigmoid(float z) {
    float z2 = z * z;
    float t = fmaf(z2, 2.0833333e-3f, -2.0833334e-2f);
    t = fmaf(z2, t, 0.25f);
    return fmaf(z, t, 0.5f);
}
__device__ __forceinline__ float felu(float z) {
    float p = fmaf(z, 8.3333333e-3f, 4.1666667e-2f);
    p = fmaf(z, p, 1.6666667e-1f);
    p = fmaf(z, p, 0.5f);
    p = fmaf(z, p, 1.0f);
    p = z * p;
    return z > 0.f ? z : p;
}
__device__ __forceinline__ void mma16816(float* c, uint32_t a0, uint32_t a1,
                                         uint32_t a2, uint32_t a3,
                                         uint32_t b0, uint32_t b1) {
    asm volatile(
        "mma.sync.aligned.m16n8k16.row.col.f32.f16.f16.f32 "
        "{%0,%1,%2,%3}, {%4,%5,%6,%7}, {%8,%9}, {%0,%1,%2,%3};"
        : "+f"(c[0]), "+f"(c[1]), "+f"(c[2]), "+f"(c[3])
        : "r"(a0), "r"(a1), "r"(a2), "r"(a3), "r"(b0), "r"(b1));
}
__device__ __forceinline__ void cp_async16(uint32_t saddr, const void* gptr) {
    asm volatile("cp.async.cg.shared.global [%0], [%1], 16;" :: "r"(saddr), "l"(gptr));
}
#define CP_COMMIT() asm volatile("cp.async.commit_group;" ::: "memory")
#define CP_WAIT0()  asm volatile("cp.async.wait_group 0;" ::: "memory")
#define LDMX4(a0, a1, a2, a3, p)                                                 \
    asm volatile("ldmatrix.sync.aligned.m8n8.x4.shared.b16 {%0,%1,%2,%3}, [%4];" \
                 : "=r"(a0), "=r"(a1), "=r"(a2), "=r"(a3) : "r"(p))

/* phase-1 chunk: 5 k-tiles, 2 m-tiles per warp, B from smem stage */
__device__ __forceinline__ void gemm_chunk(float* acc, uint32_t ap0, uint32_t ap1,
                                           int h, const uint2* sb) {
#pragma unroll
    for (int kt = 0; kt < 5; ++kt) {
        uint32_t a0, a1, a2, a3, c0, c1, c2, c3;
        LDMX4(a0, a1, a2, a3, ap0 + (h * 5 + kt) * 32);
        LDMX4(c0, c1, c2, c3, ap1 + (h * 5 + kt) * 32);
#pragma unroll
        for (int j = 0; j < 5; ++j) {
            uint2 bv = sb[(kt * 20 + j) * 32];
            mma16816(acc + (j * 2 + 0) * 4, a0, a1, a2, a3, bv.x, bv.y);
            mma16816(acc + (j * 2 + 1) * 4, c0, c1, c2, c3, bv.x, bv.y);
        }
    }
}
/* phase-2 gemm: full K=160, B from global */
__device__ __forceinline__ void gemm160_g(float* acc, uint32_t ap0, uint32_t ap1,
                                          const uint2* bp) {
#pragma unroll
    for (int kt = 0; kt < 10; ++kt) {
        uint32_t a0, a1, a2, a3, c0, c1, c2, c3;
        LDMX4(a0, a1, a2, a3, ap0 + kt * 32);
        LDMX4(c0, c1, c2, c3, ap1 + kt * 32);
#pragma unroll
        for (int j = 0; j < 5; ++j) {
            uint2 bv = bp[(kt * 20 + j) * 32];
            mma16816(acc + (j * 2 + 0) * 4, a0, a1, a2, a3, bv.x, bv.y);
            mma16816(acc + (j * 2 + 1) * 4, c0, c1, c2, c3, bv.x, bv.y);
        }
    }
}

/* epilogue helpers */
__device__ __forceinline__ void epi1_step(int jv, float b2x, float b2y,
                                          float wgx, float wgy, float bgx, float bgy,
                                          float* acc, const float* xvv,
                                          const float* c0v, float* s1v, float* s2v) {
#pragma unroll
    for (int ri = 0; ri < 4; ++ri) {
        int idx = (jv * 2 + (ri >> 1)) * 4 + (ri & 1) * 2;
        float xv = xvv[ri];
        float a2 = acc[idx] + b2x;
        float gv = fsigmoid(fmaf(xv, wgx, bgx));
        float ft = fmaf(gv, a2 - xv, xv);
        acc[idx] = ft;
        float d = ft - c0v[ri]; s1v[ri] += d; s2v[ri] = fmaf(d, d, s2v[ri]);
        a2 = acc[idx + 1] + b2y;
        gv = fsigmoid(fmaf(xv, wgy, bgy));
        ft = fmaf(gv, a2 - xv, xv);
        acc[idx + 1] = ft;
        d = ft - c0v[ri]; s1v[ri] += d; s2v[ri] = fmaf(d, d, s2v[ri]);
    }
}
__device__ __forceinline__ void epi2_step(int jv, float lgx, float lgy,
                                          float lbx, float lby, float wbf,
                                          const float* invv, const float* nmiv,
                                          const float* acc, float* comb) {
#pragma unroll
    for (int ri = 0; ri < 4; ++ri) {
        int idx = (jv * 2 + (ri >> 1)) * 4 + (ri & 1) * 2;
        float y = fmaf(fmaf(acc[idx], invv[ri], nmiv[ri]), lgx, lbx);
        comb[idx] = fmaf(wbf, y, comb[idx]);
        y = fmaf(fmaf(acc[idx + 1], invv[ri], nmiv[ri]), lgy, lby);
        comb[idx + 1] = fmaf(wbf, y, comb[idx + 1]);
    }
}

/* --------------- kernel 0: merged prep (B fragments + params) + weights --- */
__global__ void pre_kernel(const float* __restrict__ W2,
                           const float* __restrict__ oW1,
                           const float* __restrict__ oW2,
                           const float* __restrict__ oWg,
                           const float* __restrict__ W1,
                           const float* __restrict__ b1,
                           const float* __restrict__ b2,
                           const float* __restrict__ Wg,
                           const float* __restrict__ bg,
                           const float* __restrict__ lng,
                           const float* __restrict__ lnb,
                           const float* __restrict__ x,
                           const float* __restrict__ Ww,
                           const float* __restrict__ bw,
                           float* __restrict__ out_tail) {
    if (blockIdx.x >= BB) {
        int u = blockIdx.x - BB;
        int t = u >> 2, part = u & 3;               /* 35 tiles x 4 parts */
        const float* src = (t < 32) ? (W2 + (size_t)t * HH * HH)
                                    : (t == 32 ? oW1 : (t == 33 ? oW2 : oWg));
        int base = part * 1600;
        for (int k = threadIdx.x; k < 1600; k += blockDim.x) {
            int idx = base + k;
            int kt = idx / 640;
            int nt = (idx / 32) % 20;
            int l  = idx & 31;
            int k0 = kt * 16 + (l & 3) * 2;
            int n  = nt * 8 + (l >> 2);
            uint2 v;
            v.x = pack_h2(src[k0 * HH + n],       src[(k0 + 1) * HH + n]);
            v.y = pack_h2(src[(k0 + 8) * HH + n], src[(k0 + 9) * HH + n]);
            g_Bfrag[(size_t)t * 6400 + idx] = v;
        }
        if (t < FF && part == 0) {
            const float* srcs[7] = { W1 + t * HH, b1 + t * HH, b2 + t * HH,
                                     Wg + t * HH, bg + t * HH,
                                     lng + t * HH, lnb + t * HH };
            for (int jl = threadIdx.x; jl < 1120; jl += blockDim.x) {
                int a = jl / 160, c = jl - a * 160;
                int p;
                if (a < 2) {
                    p = a * 160 + c;
                } else {
                    int g = c / 40, rem = c - g * 40;
                    int j = rem >> 3, tt = (rem >> 1) & 3, e = rem & 1;
                    p = 320 + (a - 2) * 192 + g * 48 + tt * 12 + j * 2 + e;
                }
                g_Par[t * 1280 + p] = srcs[a][c];
            }
        }
        return;
    }
    int b = blockIdx.x;
    int tid = threadIdx.x;
    int c = tid & 31, g = tid >> 5;
    const float* xb = x + b * (TT * FF);
    float acc = 0.f;
#pragma unroll 4
    for (int r = g; r < TT * FF; r += 8) acc = fmaf(xb[r], Ww[r * FF + c], acc);
    __shared__ float red[8][32];
    red[g][c] = acc;
    __syncthreads();
    if (tid < 32) {
        float s = 0.f;
#pragma unroll
        for (int i = 0; i < 8; ++i) s += red[i][tid];
        s += bw[tid];
        float m = s;
#pragma unroll
        for (int o = 16; o; o >>= 1) m = fmaxf(m, __shfl_xor_sync(0xffffffffu, m, o));
        float e = expf(s - m);
        float se = e;
#pragma unroll
        for (int o = 16; o; o >>= 1) se += __shfl_xor_sync(0xffffffffu, se, o);
        float w = e / se;
        g_weights[b * 32 + tid] = w;
        out_tail[b * 32 + tid] = w;
    }
}

/* ------------------------- kernel 1: fused VSN (HMMA) ---------------------
   SMEM (bytes):
     xs      [0,       8448)   64 x 33 fp32
     eaA     [8448,   29952)   64 x 168 fp16
     red     [29952,  32000)   64 x 8 fp32
     mred    [32000,  32512)   64 x 2 fp32
     pbuf    [32512,  42752)   2 x 5120 param pack
     Bstage  [42752,  93952)   2 x 25600 cp.async double buffer (phase 1)
     eaB     [42752,  64256)   64 x 168 fp16  (phase 2, aliases Bstage)
     scratch [64256, 106240)   64 x 164 fp32  (phase 2, aliases Bstage)       */
#define OFF_EAA  8448
#define OFF_RED  29952
#define OFF_MRED 32000
#define OFF_PBUF 32512
#define PBF      1280            /* pbuf stride in floats */
#define OFF_BST  42752
#define CHKB     25600
#define OFF_EAB  42752
#define OFF_SCR  64256
#define SMEM_TOTAL 106240

__global__ void __launch_bounds__(NTH, 2)
fused_mma(const float* __restrict__ x,
          const float* __restrict__ ob1, const float* __restrict__ ob2,
          const float* __restrict__ obg,
          const float* __restrict__ olng, const float* __restrict__ olnb,
          float* __restrict__ out) {
    extern __shared__ char smem[];
    float*  xs      = (float*)smem;
    __half* eaA     = (__half*)(smem + OFF_EAA);
    float*  red     = (float*)(smem + OFF_RED);
    float*  mred    = (float*)(smem + OFF_MRED);
    __half* eaB     = (__half*)(smem + OFF_EAB);
    float*  scratch = (float*)(smem + OFF_SCR);
    const uint32_t sbase = smem_u32(smem);

    const int tid = threadIdx.x;
    const int l = tid & 31, wid = tid >> 5;
    const int mg = wid >> 2, nhq = wid & 3;      /* 2 row-groups x 4 col-groups */
    const int rA = mg * 32 + (l >> 2);
    int rr[4];
    rr[0] = rA; rr[1] = rA + 8; rr[2] = rA + 16; rr[3] = rA + 24;
    const int colbq = nhq * 40;
    const int colt = (l & 3) * 2;
    const int pbase12 = nhq * 48 + (l & 3) * 12; /* fragment-major param base */
    const int m0 = blockIdx.x * TM;
    const int bb = blockIdx.x >> 2;

    const int lrow = mg * 32 + (l & 15);
    const int lcol = (l >> 4) * 8;
    const uint32_t aAp0 = sbase + OFF_EAA + (lrow * EAS + lcol) * 2;
    const uint32_t aAp1 = aAp0 + 16 * EAS * 2;
    const uint32_t aBp0 = sbase + OFF_EAB + (lrow * EAS + lcol) * 2;
    const uint32_t aBp1 = aBp0 + 16 * EAS * 2;
    const int sboff = nhq * 160 + l;             /* uint2 elements */

    const int grow = tid >> 2;
    const int gcb = (tid & 3) * 40;

#define HBAR() asm volatile("bar.sync %0, 128;" :: "r"(1 + mg) : "memory")

    {
        const float4* xsrc = (const float4*)(x + (size_t)m0 * FF);
        for (int i = tid; i < TM * FF / 4; i += NTH) {
            float4 v = xsrc[i];
            float* d = xs + (i >> 3) * XSTR + ((i & 7) << 2);
            d[0] = v.x; d[1] = v.y; d[2] = v.z; d[3] = v.w;
        }
    }
    /* preload B chunk 0 + params f=0 */
    {
        const uint4* gsrc = (const uint4*)g_Bfrag;
        for (int j = tid; j < 1600; j += NTH)
            cp_async16(sbase + OFF_BST + j * 16, gsrc + j);
        const float4* psrc = (const float4*)g_Par;
        for (int j = tid; j < 320; j += NTH)
            cp_async16(sbase + OFF_PBUF + j * 16, psrc + j);
        CP_COMMIT();
    }
    float comb[40];
#pragma unroll
    for (int i = 0; i < 40; ++i) comb[i] = 0.f;
    CP_WAIT0();
    __syncthreads();

    float acc[40];

    /* ========================= phase 1: f loop ============================ */
    for (int f = 0; f < FF; ++f) {
        const float* pb = (const float*)(smem + OFF_PBUF) + (f & 1) * PBF;
        float wbf = g_weights[bb * FF + f];

        /* A = elu(x[.,f]*W1[f,:]+b1[f,:]) -> eaA (params from smem) */
        {
            const float xvg = xs[grow * XSTR + f];
            const float4* W1f = (const float4*)(pb + gcb);
            const float4* b1f = (const float4*)(pb + 160 + gcb);
            uint4* eg = (uint4*)(eaA + grow * EAS + gcb);
#pragma unroll
            for (int q = 0; q < 5; ++q) {
                float4 w0 = W1f[2 * q],     bb0 = b1f[2 * q];
                float4 w1 = W1f[2 * q + 1], bb1 = b1f[2 * q + 1];
                uint4 o;
                o.x = pack_h2(felu(fmaf(xvg, w0.x, bb0.x)), felu(fmaf(xvg, w0.y, bb0.y)));
                o.y = pack_h2(felu(fmaf(xvg, w0.z, bb0.z)), felu(fmaf(xvg, w0.w, bb0.w)));
                o.z = pack_h2(felu(fmaf(xvg, w1.x, bb1.x)), felu(fmaf(xvg, w1.y, bb1.y)));
                o.w = pack_h2(felu(fmaf(xvg, w1.z, bb1.z)), felu(fmaf(xvg, w1.w, bb1.w)));
                eg[q] = o;
            }
        }

#pragma unroll
        for (int i = 0; i < 40; ++i) acc[i] = 0.f;

#pragma unroll
        for (int h = 0; h < 2; ++h) {
            const int c = f * 2 + h;
            CP_WAIT0();
            __syncthreads();
            if (c + 1 < 64) {
                const uint4* gsrc = (const uint4*)g_Bfrag + (size_t)(c + 1) * 1600;
                const uint32_t dst = sbase + OFF_BST + ((c + 1) & 1) * CHKB;
                for (int j = tid; j < 1600; j += NTH)
                    cp_async16(dst + j * 16, gsrc + j);
                if (h == 0 && f + 1 < FF) {
                    const float4* psrc = (const float4*)g_Par + (size_t)(f + 1) * 320;
                    const uint32_t pdst = sbase + OFF_PBUF + ((f + 1) & 1) * (PBF * 4);
                    for (int j = tid; j < 320; j += NTH)
                        cp_async16(pdst + j * 16, psrc + j);
                }
                CP_COMMIT();
            }
            const uint2* sb = (const uint2*)(smem + OFF_BST + (c & 1) * CHKB) + sboff;
            gemm_chunk(acc, aAp0, aAp1, h, sb);
        }

        /* epilogue part 1: a2 -> gate -> feat (in acc), centered stats */
        float xvv[4], c0v[4], s1v[4], s2v[4];
#pragma unroll
        for (int ri = 0; ri < 4; ++ri) {
            xvv[ri] = xs[rr[ri] * XSTR + f];
            c0v[ri] = 0.5f * xvv[ri];
            s1v[ri] = 0.f; s2v[ri] = 0.f;
        }
        {
            const float* pB2 = pb + 320 + pbase12;
            const float* pWg = pb + 512 + pbase12;
            const float* pBg = pb + 704 + pbase12;
#pragma unroll
            for (int jp = 0; jp < 2; ++jp) {
                float4 v2 = *(const float4*)(pB2 + jp * 4);
                float4 vg = *(const float4*)(pWg + jp * 4);
                float4 vb = *(const float4*)(pBg + jp * 4);
                epi1_step(2 * jp,     v2.x, v2.y, vg.x, vg.y, vb.x, vb.y,
                          acc, xvv, c0v, s1v, s2v);
                epi1_step(2 * jp + 1, v2.z, v2.w, vg.z, vg.w, vb.z, vb.w,
                          acc, xvv, c0v, s1v, s2v);
            }
            float2 v2 = *(const float2*)(pB2 + 8);
            float2 vg = *(const float2*)(pWg + 8);
            float2 vb = *(const float2*)(pBg + 8);
            epi1_step(4, v2.x, v2.y, vg.x, vg.y, vb.x, vb.y,
                      acc, xvv, c0v, s1v, s2v);
        }
#pragma unroll
        for (int ri = 0; ri < 4; ++ri) {
#pragma unroll
            for (int o = 1; o < 4; o <<= 1) {
                s1v[ri] += __shfl_xor_sync(0xffffffffu, s1v[ri], o);
                s2v[ri] += __shfl_xor_sync(0xffffffffu, s2v[ri], o);
            }
        }
        if ((l & 3) == 0) {
#pragma unroll
            for (int ri = 0; ri < 4; ++ri)
                *(float2*)(red + rr[ri] * 8 + nhq * 2) = make_float2(s1v[ri], s2v[ri]);
        }
        HBAR();
        float invv[4], nmiv[4];
#pragma unroll
        for (int ri = 0; ri < 4; ++ri) {
            float4 qa = *(const float4*)(red + rr[ri] * 8);
            float4 qb = *(const float4*)(red + rr[ri] * 8 + 4);
            float S1 = (qa.x + qa.z) + (qb.x + qb.z);
            float S2 = (qa.y + qa.w) + (qb.y + qb.w);
            float dm = S1 * (1.f / 160.f);
            float var = fmaf(-dm, dm, S2 * (1.f / 160.f));
            invv[ri] = rsqrtf(var + 1e-3f);
            nmiv[ri] = -(c0v[ri] + dm) * invv[ri];
        }
        {
            const float* pLg = pb + 896 + pbase12;
            const float* pLb = pb + 1088 + pbase12;
#pragma unroll
            for (int jp = 0; jp < 2; ++jp) {
                float4 vg = *(const float4*)(pLg + jp * 4);
                float4 vb = *(const float4*)(pLb + jp * 4);
                epi2_step(2 * jp,     vg.x, vg.y, vb.x, vb.y, wbf, invv, nmiv, acc, comb);
                epi2_step(2 * jp + 1, vg.z, vg.w, vb.z, vb.w, wbf, invv, nmiv, acc, comb);
            }
            float2 vg = *(const float2*)(pLg + 8);
            float2 vb = *(const float2*)(pLb + 8);
            epi2_step(4, vg.x, vg.y, vb.x, vb.y, wbf, invv, nmiv, acc, comb);
        }
        HBAR();   /* all half-warps past GEMM+epilogue before next A-gen */
    }

    /* ========================= phase 2: output MLP ======================== */
    __syncthreads();   /* CTA-wide: Bstage dead before eaB/scratch aliases */
#pragma unroll
    for (int j = 0; j < 5; ++j) {
#pragma unroll
        for (int ri = 0; ri < 4; ++ri) {
            int idx = (j * 2 + (ri >> 1)) * 4 + (ri & 1) * 2;
            *(uint32_t*)(eaA + rr[ri] * EAS + colbq + j * 8 + colt) =
                pack_h2(comb[idx], comb[idx + 1]);
        }
    }
    HBAR();

    /* GEMM1: h1 = elu(comb @ oW1 + ob1) -> eaB */
#pragma unroll
    for (int i = 0; i < 40; ++i) acc[i] = 0.f;
    gemm160_g(acc, aAp0, aAp1, g_Bfrag + 32u * 6400 + sboff);
#pragma unroll
    for (int j = 0; j < 5; ++j) {
        int col = colbq + j * 8 + colt;
        float2 vb = *(const float2*)(ob1 + col);
#pragma unroll
        for (int ri = 0; ri < 4; ++ri) {
            int idx = (j * 2 + (ri >> 1)) * 4 + (ri & 1) * 2;
            *(uint32_t*)(eaB + rr[ri] * EAS + col) =
                pack_h2(felu(acc[idx] + vb.x), felu(acc[idx + 1] + vb.y));
        }
    }
    HBAR();

    /* GEMM2: oa = h1 @ oW2 + ob2 -> scratch */
#pragma unroll
    for (int i = 0; i < 40; ++i) acc[i] = 0.f;
    gemm160_g(acc, aBp0, aBp1, g_Bfrag + 33u * 6400 + sboff);
#pragma unroll
    for (int j = 0; j < 5; ++j) {
        int col = colbq + j * 8 + colt;
        float2 vb = *(const float2*)(ob2 + col);
#pragma unroll
        for (int ri = 0; ri < 4; ++ri) {
            int idx = (j * 2 + (ri >> 1)) * 4 + (ri & 1) * 2;
            *(float2*)(scratch + rr[ri] * SCS + col) =
                make_float2(acc[idx] + vb.x, acc[idx + 1] + vb.y);
        }
    }

    /* GEMM3: og = sigmoid(comb @ oWg + obg); v = og*(oa-comb)+comb */
#pragma unroll
    for (int i = 0; i < 40; ++i) acc[i] = 0.f;
    gemm160_g(acc, aAp0, aAp1, g_Bfrag + 34u * 6400 + sboff);
    {
        float s1v[4] = {0.f, 0.f, 0.f, 0.f};
        float s2v[4] = {0.f, 0.f, 0.f, 0.f};
#pragma unroll
        for (int j = 0; j < 5; ++j) {
            int col = colbq + j * 8 + colt;
            float2 vb = *(const float2*)(obg + col);
#pragma unroll
            for (int ri = 0; ri < 4; ++ri) {
                int idx = (j * 2 + (ri >> 1)) * 4 + (ri & 1) * 2;
                float2 oa = *(float2*)(scratch + rr[ri] * SCS + col);
                float og = fsigmoid(acc[idx] + vb.x);
                float c = comb[idx];
                float v = fmaf(og, oa.x - c, c);
                oa.x = v; s1v[ri] += v; s2v[ri] = fmaf(v, v, s2v[ri]);
                og = fsigmoid(acc[idx + 1] + vb.y);
                c = comb[idx + 1];
                v = fmaf(og, oa.y - c, c);
                oa.y = v; s1v[ri] += v; s2v[ri] = fmaf(v, v, s2v[ri]);
                *(float2*)(scratch + rr[ri] * SCS + col) = oa;
            }
        }
#pragma unroll
        for (int ri = 0; ri < 4; ++ri) {
#pragma unroll
            for (int o = 1; o < 4; o <<= 1) {
                s1v[ri] += __shfl_xor_sync(0xffffffffu, s1v[ri], o);
                s2v[ri] += __shfl_xor_sync(0xffffffffu, s2v[ri], o);
            }
        }
        if ((l & 3) == 0) {
#pragma unroll
            for (int ri = 0; ri < 4; ++ri)
                *(float2*)(red + rr[ri] * 8 + nhq * 2) = make_float2(s1v[ri], s2v[ri]);
        }
        HBAR();
        if ((l & 3) == 0 && nhq == 0) {
#pragma unroll
            for (int ri = 0; ri < 4; ++ri) {
                float4 qa = *(const float4*)(red + rr[ri] * 8);
                float4 qb = *(const float4*)(red + rr[ri] * 8 + 4);
                float S1 = (qa.x + qa.z) + (qb.x + qb.z);
                float S2 = (qa.y + qa.w) + (qb.y + qb.w);
                float mean = S1 * (1.f / 160.f);
                float var = fmaf(-mean, mean, S2 * (1.f / 160.f));
                *(float2*)(mred + rr[ri] * 2) = make_float2(mean, rsqrtf(var + 1e-3f));
            }
        }
        HBAR();
    }

    /* final LN + coalesced store (rows are half-local: tid>>2) */
    {
        const int row = tid >> 2;
        const int cb2 = (tid & 3) * 40;
        float2 mi = *(const float2*)(mred + row * 2);
        const float mean = mi.x, inv = mi.y;
        const float* sv = scratch + row * SCS + cb2;
        const float4* lg4 = (const float4*)(olng + cb2);
        const float4* lb4 = (const float4*)(olnb + cb2);
        float4* orow = (float4*)(out + (size_t)(m0 + row) * HH + cb2);
#pragma unroll
        for (int q = 0; q < 10; ++q) {
            float4 g4 = lg4[q], bq = lb4[q], o;
            o.x = fmaf((sv[q * 4 + 0] - mean) * inv, g4.x, bq.x);
            o.y = fmaf((sv[q * 4 + 1] - mean) * inv, g4.y, bq.y);
            o.z = fmaf((sv[q * 4 + 2] - mean) * inv, g4.z, bq.z);
            o.w = fmaf((sv[q * 4 + 3] - mean) * inv, g4.w, bq.w);
            orow[q] = o;
        }
    }
#undef HBAR
}

/* --------------------------------- launch --------------------------------- */
extern "C" void kernel_launch(void* const* d_in, const int* in_sizes, int n_in,
                              void* d_out, int out_size) {
    const float* x    = (const float*)d_in[0];
    const float* W1   = (const float*)d_in[1];
    const float* b1   = (const float*)d_in[2];
    const float* W2   = (const float*)d_in[3];
    const float* b2   = (const float*)d_in[4];
    const float* Wg   = (const float*)d_in[5];
    const float* bg   = (const float*)d_in[6];
    const float* lng  = (const float*)d_in[7];
    const float* lnb  = (const float*)d_in[8];
    const float* Ww   = (const float*)d_in[9];
    const float* bw   = (const float*)d_in[10];
    const float* oW1  = (const float*)d_in[11];
    const float* ob1  = (const float*)d_in[12];
    const float* oW2  = (const float*)d_in[13];
    const float* ob2  = (const float*)d_in[14];
    const float* oWg  = (const float*)d_in[15];
    const float* obg  = (const float*)d_in[16];
    const float* olng = (const float*)d_in[17];
    const float* olnb = (const float*)d_in[18];
    float* out = (float*)d_out;

    cudaFuncSetAttribute(fused_mma, cudaFuncAttributeMaxDynamicSharedMemorySize,
                         SMEM_TOTAL);

    pre_kernel<<<BB + 140, 256>>>(W2, oW1, oW2, oWg,
                                  W1, b1, b2, Wg, bg, lng, lnb,
                                  x, Ww, bw, out + (size_t)BB * TT * HH);
    fused_mma<<<(BB * TT) / TM, NTH, SMEM_TOTAL>>>(
        x, ob1, ob2, obg, olng, olnb, out);
}

// round 10
// speedup vs baseline: 1.0418x; 1.0348x over previous
#include <cuda_runtime.h>
#include <cuda_fp16.h>
#include <stdint.h>

#define FF 32
#define HH 160
#define BB 64
#define TT 256
#define TM 64
#define NTH 256
#define EAS 168      /* half stride for A images (>=160, ldmatrix-friendly) */
#define XSTR 33      /* x tile row stride (floats) */
#define SCS 164      /* scratch row stride (floats) */

typedef unsigned long long u64;

__device__ float g_weights[BB * FF];
/* B fragments: [t(35)][kt(10)][nt(20)][lane(32)] -> uint2 {b0,b1} */
__device__ __align__(16) uint2 g_Bfrag[35 * 6400];
/* per-f parameter pack, 1280 floats per f:
   [0,160)=W1  [160,320)=b1  then 5 fragment-major arrays of 192 floats:
   b2@320, Wg@512, bg@704, lng@896, lnb@1088.
   fragment-major: pos = g*48 + tt*12 + j*2 + e for col = g*40 + j*8 + tt*2 + e */
__device__ __align__(16) float g_Par[FF * 1280];

/* ------------------------------ helpers ---------------------------------- */
__device__ __forceinline__ uint32_t smem_u32(const void* p) {
    uint32_t a;
    asm("{ .reg .u64 t; cvta.to.shared.u64 t, %1; cvt.u32.u64 %0, t; }" : "=r"(a) : "l"(p));
    return a;
}
__device__ __forceinline__ uint32_t pack_h2(float a, float b) {
    __half2 h = __floats2half2_rn(a, b);
    return *reinterpret_cast<uint32_t*>(&h);
}
/* packed f32x2 primitives (Blackwell) */
__device__ __forceinline__ u64 packf2(float lo, float hi) {
    u64 r;
    asm("mov.b64 %0, {%1, %2};" : "=l"(r) : "f"(lo), "f"(hi));
    return r;
}
__device__ __forceinline__ void unpackf2(float& lo, float& hi, u64 v) {
    asm("mov.b64 {%0, %1}, %2;" : "=f"(lo), "=f"(hi) : "l"(v));
}
#define FMA2(d, a, b, c) asm("fma.rn.f32x2 %0, %1, %2, %3;" : "=l"(d) : "l"(a), "l"(b), "l"(c))
#define ADD2(d, a, b)    asm("add.rn.f32x2 %0, %1, %2;" : "=l"(d) : "l"(a), "l"(b))
#define MUL2(d, a, b)    asm("mul.rn.f32x2 %0, %1, %2;" : "=l"(d) : "l"(a), "l"(b))

/* packed sigmoid (|z| small): z*(0.25 - z^2/48*(1 - z^2/4.8...)) poly as before */
__device__ __forceinline__ u64 fsig2(u64 z, u64 SC1, u64 SC2, u64 SC3, u64 SCH) {
    u64 z2, t;
    MUL2(z2, z, z);
    FMA2(t, z2, SC1, SC2);
    FMA2(t, z2, t, SC3);
    FMA2(t, z, t, SCH);
    return t;
}
/* packed elu -> fp16x2: z>=0 ? z : expm1(z) (5-term series) */
__device__ __forceinline__ uint32_t agen2(u64 xg2, u64 w, u64 b,
                                          u64 C120, u64 C24, u64 C6, u64 SCH) {
    u64 z, z2, qq, p;
    FMA2(z, xg2, w, b);
    MUL2(z2, z, z);
    FMA2(qq, z, C120, C24);
    FMA2(qq, z, qq, C6);
    FMA2(qq, z, qq, SCH);
    FMA2(p, z2, qq, z);
    float zl, zh, pl, ph;
    unpackf2(zl, zh, z);
    unpackf2(pl, ph, p);
    float rl = zl > 0.f ? zl : pl;
    float rh = zh > 0.f ? zh : ph;
    return pack_h2(rl, rh);
}
/* scalar versions for phase 2 (cold) */
__device__ __forceinline__ float fsigmoid(float z) {
    float z2 = z * z;
    float t = fmaf(z2, 2.0833333e-3f, -2.0833334e-2f);
    t = fmaf(z2, t, 0.25f);
    return fmaf(z, t, 0.5f);
}
__device__ __forceinline__ float felu(float z) {
    float p = fmaf(z, 8.3333333e-3f, 4.1666667e-2f);
    p = fmaf(z, p, 1.6666667e-1f);
    p = fmaf(z, p, 0.5f);
    p = fmaf(z, p, 1.0f);
    p = z * p;
    return z > 0.f ? z : p;
}
__device__ __forceinline__ void mma16816(float* c, uint32_t a0, uint32_t a1,
                                         uint32_t a2, uint32_t a3,
                                         uint32_t b0, uint32_t b1) {
    asm volatile(
        "mma.sync.aligned.m16n8k16.row.col.f32.f16.f16.f32 "
        "{%0,%1,%2,%3}, {%4,%5,%6,%7}, {%8,%9}, {%0,%1,%2,%3};"
        : "+f"(c[0]), "+f"(c[1]), "+f"(c[2]), "+f"(c[3])
        : "r"(a0), "r"(a1), "r"(a2), "r"(a3), "r"(b0), "r"(b1));
}
__device__ __forceinline__ void cp_async16(uint32_t saddr, const void* gptr) {
    asm volatile("cp.async.cg.shared.global [%0], [%1], 16;" :: "r"(saddr), "l"(gptr));
}
#define CP_COMMIT() asm volatile("cp.async.commit_group;" ::: "memory")
#define CP_WAIT0()  asm volatile("cp.async.wait_group 0;" ::: "memory")
#define LDMX4(a0, a1, a2, a3, p)                                                 \
    asm volatile("ldmatrix.sync.aligned.m8n8.x4.shared.b16 {%0,%1,%2,%3}, [%4];" \
                 : "=r"(a0), "=r"(a1), "=r"(a2), "=r"(a3) : "r"(p))

/* phase-1 chunk: 5 k-tiles, 2 m-tiles per warp, B from smem stage */
__device__ __forceinline__ void gemm_chunk(float* acc, uint32_t ap0, uint32_t ap1,
                                           int h, const uint2* sb) {
#pragma unroll
    for (int kt = 0; kt < 5; ++kt) {
        uint32_t a0, a1, a2, a3, c0, c1, c2, c3;
        LDMX4(a0, a1, a2, a3, ap0 + (h * 5 + kt) * 32);
        LDMX4(c0, c1, c2, c3, ap1 + (h * 5 + kt) * 32);
#pragma unroll
        for (int j = 0; j < 5; ++j) {
            uint2 bv = sb[(kt * 20 + j) * 32];
            mma16816(acc + (j * 2 + 0) * 4, a0, a1, a2, a3, bv.x, bv.y);
            mma16816(acc + (j * 2 + 1) * 4, c0, c1, c2, c3, bv.x, bv.y);
        }
    }
}
/* phase-2 gemm: full K=160, B from global */
__device__ __forceinline__ void gemm160_g(float* acc, uint32_t ap0, uint32_t ap1,
                                          const uint2* bp) {
#pragma unroll
    for (int kt = 0; kt < 10; ++kt) {
        uint32_t a0, a1, a2, a3, c0, c1, c2, c3;
        LDMX4(a0, a1, a2, a3, ap0 + kt * 32);
        LDMX4(c0, c1, c2, c3, ap1 + kt * 32);
#pragma unroll
        for (int j = 0; j < 5; ++j) {
            uint2 bv = bp[(kt * 20 + j) * 32];
            mma16816(acc + (j * 2 + 0) * 4, a0, a1, a2, a3, bv.x, bv.y);
            mma16816(acc + (j * 2 + 1) * 4, c0, c1, c2, c3, bv.x, bv.y);
        }
    }
}

/* --------------- kernel 0: merged prep (B fragments + params) + weights --- */
__global__ void pre_kernel(const float* __restrict__ W2,
                           const float* __restrict__ oW1,
                           const float* __restrict__ oW2,
                           const float* __restrict__ oWg,
                           const float* __restrict__ W1,
                           const float* __restrict__ b1,
                           const float* __restrict__ b2,
                           const float* __restrict__ Wg,
                           const float* __restrict__ bg,
                           const float* __restrict__ lng,
                           const float* __restrict__ lnb,
                           const float* __restrict__ x,
                           const float* __restrict__ Ww,
                           const float* __restrict__ bw,
                           float* __restrict__ out_tail) {
    if (blockIdx.x >= BB) {
        int u = blockIdx.x - BB;
        int t = u >> 2, part = u & 3;               /* 35 tiles x 4 parts */
        const float* src = (t < 32) ? (W2 + (size_t)t * HH * HH)
                                    : (t == 32 ? oW1 : (t == 33 ? oW2 : oWg));
        int base = part * 1600;
        for (int k = threadIdx.x; k < 1600; k += blockDim.x) {
            int idx = base + k;
            int kt = idx / 640;
            int nt = (idx / 32) % 20;
            int l  = idx & 31;
            int k0 = kt * 16 + (l & 3) * 2;
            int n  = nt * 8 + (l >> 2);
            uint2 v;
            v.x = pack_h2(src[k0 * HH + n],       src[(k0 + 1) * HH + n]);
            v.y = pack_h2(src[(k0 + 8) * HH + n], src[(k0 + 9) * HH + n]);
            g_Bfrag[(size_t)t * 6400 + idx] = v;
        }
        if (t < FF && part == 0) {
            const float* srcs[7] = { W1 + t * HH, b1 + t * HH, b2 + t * HH,
                                     Wg + t * HH, bg + t * HH,
                                     lng + t * HH, lnb + t * HH };
            for (int jl = threadIdx.x; jl < 1120; jl += blockDim.x) {
                int a = jl / 160, c = jl - a * 160;
                int p;
                if (a < 2) {
                    p = a * 160 + c;
                } else {
                    int g = c / 40, rem = c - g * 40;
                    int j = rem >> 3, tt = (rem >> 1) & 3, e = rem & 1;
                    p = 320 + (a - 2) * 192 + g * 48 + tt * 12 + j * 2 + e;
                }
                g_Par[t * 1280 + p] = srcs[a][c];
            }
        }
        return;
    }
    int b = blockIdx.x;
    int tid = threadIdx.x;
    int c = tid & 31, g = tid >> 5;
    const float* xb = x + b * (TT * FF);
    float acc = 0.f;
#pragma unroll 4
    for (int r = g; r < TT * FF; r += 8) acc = fmaf(xb[r], Ww[r * FF + c], acc);
    __shared__ float red[8][32];
    red[g][c] = acc;
    __syncthreads();
    if (tid < 32) {
        float s = 0.f;
#pragma unroll
        for (int i = 0; i < 8; ++i) s += red[i][tid];
        s += bw[tid];
        float m = s;
#pragma unroll
        for (int o = 16; o; o >>= 1) m = fmaxf(m, __shfl_xor_sync(0xffffffffu, m, o));
        float e = expf(s - m);
        float se = e;
#pragma unroll
        for (int o = 16; o; o >>= 1) se += __shfl_xor_sync(0xffffffffu, se, o);
        float w = e / se;
        g_weights[b * 32 + tid] = w;
        out_tail[b * 32 + tid] = w;
    }
}

/* ------------------------- kernel 1: fused VSN (HMMA) --------------------- */
#define OFF_EAA  8448
#define OFF_RED  29952
#define OFF_MRED 32000
#define OFF_PBUF 32512
#define PBF      1280            /* pbuf stride in floats */
#define OFF_BST  42752
#define CHKB     25600
#define OFF_EAB  42752
#define OFF_SCR  64256
#define SMEM_TOTAL 106240

__global__ void __launch_bounds__(NTH, 2)
fused_mma(const float* __restrict__ x,
          const float* __restrict__ ob1, const float* __restrict__ ob2,
          const float* __restrict__ obg,
          const float* __restrict__ olng, const float* __restrict__ olnb,
          float* __restrict__ out) {
    extern __shared__ char smem[];
    float*  xs      = (float*)smem;
    __half* eaA     = (__half*)(smem + OFF_EAA);
    float*  red     = (float*)(smem + OFF_RED);
    float*  mred    = (float*)(smem + OFF_MRED);
    __half* eaB     = (__half*)(smem + OFF_EAB);
    float*  scratch = (float*)(smem + OFF_SCR);
    const uint32_t sbase = smem_u32(smem);

    const int tid = threadIdx.x;
    const int l = tid & 31, wid = tid >> 5;
    const int mg = wid >> 2, nhq = wid & 3;      /* 2 row-groups x 4 col-groups */
    const int rA = mg * 32 + (l >> 2);
    int rr[4];
    rr[0] = rA; rr[1] = rA + 8; rr[2] = rA + 16; rr[3] = rA + 24;
    const int colbq = nhq * 40;
    const int colt = (l & 3) * 2;
    const int pbase12 = nhq * 48 + (l & 3) * 12; /* fragment-major param base */
    const int m0 = blockIdx.x * TM;
    const int bb = blockIdx.x >> 2;

    const int lrow = mg * 32 + (l & 15);
    const int lcol = (l >> 4) * 8;
    const uint32_t aAp0 = sbase + OFF_EAA + (lrow * EAS + lcol) * 2;
    const uint32_t aAp1 = aAp0 + 16 * EAS * 2;
    const uint32_t aBp0 = sbase + OFF_EAB + (lrow * EAS + lcol) * 2;
    const uint32_t aBp1 = aBp0 + 16 * EAS * 2;
    const int sboff = nhq * 160 + l;             /* uint2 elements */

    const int grow = tid >> 2;
    const int gcb = (tid & 3) * 40;

    /* packed constants */
    const u64 SC1  = packf2(2.0833333e-3f, 2.0833333e-3f);
    const u64 SC2  = packf2(-2.0833334e-2f, -2.0833334e-2f);
    const u64 SC3  = packf2(0.25f, 0.25f);
    const u64 SCH  = packf2(0.5f, 0.5f);
    const u64 C120 = packf2(8.3333333e-3f, 8.3333333e-3f);
    const u64 C24  = packf2(4.1666667e-2f, 4.1666667e-2f);
    const u64 C6   = packf2(1.6666667e-1f, 1.6666667e-1f);

#define HBAR() asm volatile("bar.sync %0, 128;" :: "r"(1 + mg) : "memory")

    {
        const float4* xsrc = (const float4*)(x + (size_t)m0 * FF);
        for (int i = tid; i < TM * FF / 4; i += NTH) {
            float4 v = xsrc[i];
            float* d = xs + (i >> 3) * XSTR + ((i & 7) << 2);
            d[0] = v.x; d[1] = v.y; d[2] = v.z; d[3] = v.w;
        }
    }
    /* preload B chunk 0 + params f=0 */
    {
        const uint4* gsrc = (const uint4*)g_Bfrag;
        for (int j = tid; j < 1600; j += NTH)
            cp_async16(sbase + OFF_BST + j * 16, gsrc + j);
        const float4* psrc = (const float4*)g_Par;
        for (int j = tid; j < 320; j += NTH)
            cp_async16(sbase + OFF_PBUF + j * 16, psrc + j);
        CP_COMMIT();
    }
    u64 comb2[20];
#pragma unroll
    for (int i = 0; i < 20; ++i) comb2[i] = 0ull;
    CP_WAIT0();
    __syncthreads();

    float acc[40];

    /* ========================= phase 1: f loop ============================ */
    for (int f = 0; f < FF; ++f) {
        const float* pb = (const float*)(smem + OFF_PBUF) + (f & 1) * PBF;
        float wbf = g_weights[bb * FF + f];

        /* A = elu(x[.,f]*W1[f,:]+b1[f,:]) -> eaA, packed math */
        {
            const float xvg = xs[grow * XSTR + f];
            const u64 xg2 = packf2(xvg, xvg);
            const u64* W1u = (const u64*)(pb + gcb);
            const u64* b1u = (const u64*)(pb + 160 + gcb);
            uint4* eg = (uint4*)(eaA + grow * EAS + gcb);
#pragma unroll
            for (int q = 0; q < 5; ++q) {
                uint4 o;
                o.x = agen2(xg2, W1u[4 * q + 0], b1u[4 * q + 0], C120, C24, C6, SCH);
                o.y = agen2(xg2, W1u[4 * q + 1], b1u[4 * q + 1], C120, C24, C6, SCH);
                o.z = agen2(xg2, W1u[4 * q + 2], b1u[4 * q + 2], C120, C24, C6, SCH);
                o.w = agen2(xg2, W1u[4 * q + 3], b1u[4 * q + 3], C120, C24, C6, SCH);
                eg[q] = o;
            }
        }

#pragma unroll
        for (int i = 0; i < 40; ++i) acc[i] = 0.f;

#pragma unroll
        for (int h = 0; h < 2; ++h) {
            const int c = f * 2 + h;
            CP_WAIT0();
            __syncthreads();
            if (c + 1 < 64) {
                const uint4* gsrc = (const uint4*)g_Bfrag + (size_t)(c + 1) * 1600;
                const uint32_t dst = sbase + OFF_BST + ((c + 1) & 1) * CHKB;
                for (int j = tid; j < 1600; j += NTH)
                    cp_async16(dst + j * 16, gsrc + j);
                if (h == 0 && f + 1 < FF) {
                    const float4* psrc = (const float4*)g_Par + (size_t)(f + 1) * 320;
                    const uint32_t pdst = sbase + OFF_PBUF + ((f + 1) & 1) * (PBF * 4);
                    for (int j = tid; j < 320; j += NTH)
                        cp_async16(pdst + j * 16, psrc + j);
                }
                CP_COMMIT();
            }
            const uint2* sb = (const uint2*)(smem + OFF_BST + (c & 1) * CHKB) + sboff;
            gemm_chunk(acc, aAp0, aAp1, h, sb);
        }

        /* epilogue part 1 (packed): a2 -> gate -> feat, centered stats */
        u64 xv2[4], nxv2[4], nc02[4], s1p[4], s2p[4];
        float c0v[4];
#pragma unroll
        for (int ri = 0; ri < 4; ++ri) {
            float xv = xs[rr[ri] * XSTR + f];
            float c0 = 0.5f * xv;
            xv2[ri]  = packf2(xv, xv);
            nxv2[ri] = packf2(-xv, -xv);
            nc02[ri] = packf2(-c0, -c0);
            c0v[ri]  = c0;
            s1p[ri] = 0ull; s2p[ri] = 0ull;
        }
        u64 featp[20];
        {
            const u64* pB2 = (const u64*)(pb + 320 + pbase12);
            const u64* pWg = (const u64*)(pb + 512 + pbase12);
            const u64* pBg = (const u64*)(pb + 704 + pbase12);
#pragma unroll
            for (int jv = 0; jv < 5; ++jv) {
                u64 b2p = pB2[jv], wgp = pWg[jv], bgp = pBg[jv];
#pragma unroll
                for (int ri = 0; ri < 4; ++ri) {
                    int idx = (jv * 2 + (ri >> 1)) * 4 + (ri & 1) * 2;
                    u64 ap = packf2(acc[idx], acc[idx + 1]);
                    u64 a2; ADD2(a2, ap, b2p);
                    u64 gz; FMA2(gz, xv2[ri], wgp, bgp);
                    u64 gv = fsig2(gz, SC1, SC2, SC3, SCH);
                    u64 dmx; ADD2(dmx, a2, nxv2[ri]);
                    u64 ft; FMA2(ft, gv, dmx, xv2[ri]);
                    featp[jv * 4 + ri] = ft;
                    u64 d; ADD2(d, ft, nc02[ri]);
                    ADD2(s1p[ri], s1p[ri], d);
                    FMA2(s2p[ri], d, d, s2p[ri]);
                }
            }
        }
        float s1v[4], s2v[4];
#pragma unroll
        for (int ri = 0; ri < 4; ++ri) {
            float a, b2_;
            unpackf2(a, b2_, s1p[ri]); s1v[ri] = a + b2_;
            unpackf2(a, b2_, s2p[ri]); s2v[ri] = a + b2_;
        }
#pragma unroll
        for (int ri = 0; ri < 4; ++ri) {
#pragma unroll
            for (int o = 1; o < 4; o <<= 1) {
                s1v[ri] += __shfl_xor_sync(0xffffffffu, s1v[ri], o);
                s2v[ri] += __shfl_xor_sync(0xffffffffu, s2v[ri], o);
            }
        }
        if ((l & 3) == 0) {
#pragma unroll
            for (int ri = 0; ri < 4; ++ri)
                *(float2*)(red + rr[ri] * 8 + nhq * 2) = make_float2(s1v[ri], s2v[ri]);
        }
        HBAR();
        u64 inv2[4], nmi2[4];
#pragma unroll
        for (int ri = 0; ri < 4; ++ri) {
            float4 qa = *(const float4*)(red + rr[ri] * 8);
            float4 qb = *(const float4*)(red + rr[ri] * 8 + 4);
            float S1 = (qa.x + qa.z) + (qb.x + qb.z);
            float S2 = (qa.y + qa.w) + (qb.y + qb.w);
            float dm = S1 * (1.f / 160.f);
            float var = fmaf(-dm, dm, S2 * (1.f / 160.f));
            float inv = rsqrtf(var + 1e-3f);
            float nmi = -(c0v[ri] + dm) * inv;
            inv2[ri] = packf2(inv, inv);
            nmi2[ri] = packf2(nmi, nmi);
        }
        {
            u64 wbf2 = packf2(wbf, wbf);
            const u64* pLg = (const u64*)(pb + 896 + pbase12);
            const u64* pLb = (const u64*)(pb + 1088 + pbase12);
#pragma unroll
            for (int jv = 0; jv < 5; ++jv) {
                u64 lgp = pLg[jv], lbp = pLb[jv];
#pragma unroll
                for (int ri = 0; ri < 4; ++ri) {
                    u64 yt; FMA2(yt, featp[jv * 4 + ri], inv2[ri], nmi2[ri]);
                    u64 y;  FMA2(y, yt, lgp, lbp);
                    FMA2(comb2[jv * 4 + ri], wbf2, y, comb2[jv * 4 + ri]);
                }
            }
        }
        HBAR();   /* all half-warps past GEMM+epilogue before next A-gen */
    }

    /* ========================= phase 2: output MLP ======================== */
    /* unpack comb2 -> float comb[40] (old idx mapping) */
    float comb[40];
#pragma unroll
    for (int jv = 0; jv < 5; ++jv)
#pragma unroll
        for (int ri = 0; ri < 4; ++ri) {
            int idx = (jv * 2 + (ri >> 1)) * 4 + (ri & 1) * 2;
            unpackf2(comb[idx], comb[idx + 1], comb2[jv * 4 + ri]);
        }

    __syncthreads();   /* CTA-wide: Bstage dead before eaB/scratch aliases */
#pragma unroll
    for (int j = 0; j < 5; ++j) {
#pragma unroll
        for (int ri = 0; ri < 4; ++ri) {
            int idx = (j * 2 + (ri >> 1)) * 4 + (ri & 1) * 2;
            *(uint32_t*)(eaA + rr[ri] * EAS + colbq + j * 8 + colt) =
                pack_h2(comb[idx], comb[idx + 1]);
        }
    }
    HBAR();

    /* GEMM1: h1 = elu(comb @ oW1 + ob1) -> eaB */
#pragma unroll
    for (int i = 0; i < 40; ++i) acc[i] = 0.f;
    gemm160_g(acc, aAp0, aAp1, g_Bfrag + 32u * 6400 + sboff);
#pragma unroll
    for (int j = 0; j < 5; ++j) {
        int col = colbq + j * 8 + colt;
        float2 vb = *(const float2*)(ob1 + col);
#pragma unroll
        for (int ri = 0; ri < 4; ++ri) {
            int idx = (j * 2 + (ri >> 1)) * 4 + (ri & 1) * 2;
            *(uint32_t*)(eaB + rr[ri] * EAS + col) =
                pack_h2(felu(acc[idx] + vb.x), felu(acc[idx + 1] + vb.y));
        }
    }
    HBAR();

    /* GEMM2: oa = h1 @ oW2 + ob2 -> scratch */
#pragma unroll
    for (int i = 0; i < 40; ++i) acc[i] = 0.f;
    gemm160_g(acc, aBp0, aBp1, g_Bfrag + 33u * 6400 + sboff);
#pragma unroll
    for (int j = 0; j < 5; ++j) {
        int col = colbq + j * 8 + colt;
        float2 vb = *(const float2*)(ob2 + col);
#pragma unroll
        for (int ri = 0; ri < 4; ++ri) {
            int idx = (j * 2 + (ri >> 1)) * 4 + (ri & 1) * 2;
            *(float2*)(scratch + rr[ri] * SCS + col) =
                make_float2(acc[idx] + vb.x, acc[idx + 1] + vb.y);
        }
    }

    /* GEMM3: og = sigmoid(comb @ oWg + obg); v = og*(oa-comb)+comb */
#pragma unroll
    for (int i = 0; i < 40; ++i) acc[i] = 0.f;
    gemm160_g(acc, aAp0, aAp1, g_Bfrag + 34u * 6400 + sboff);
    {
        float s1v[4] = {0.f, 0.f, 0.f, 0.f};
        float s2v[4] = {0.f, 0.f, 0.f, 0.f};
#pragma unroll
        for (int j = 0; j < 5; ++j) {
            int col = colbq + j * 8 + colt;
            float2 vb = *(const float2*)(obg + col);
#pragma unroll
            for (int ri = 0; ri < 4; ++ri) {
                int idx = (j * 2 + (ri >> 1)) * 4 + (ri & 1) * 2;
                float2 oa = *(float2*)(scratch + rr[ri] * SCS + col);
                float og = fsigmoid(acc[idx] + vb.x);
                float c = comb[idx];
                float v = fmaf(og, oa.x - c, c);
                oa.x = v; s1v[ri] += v; s2v[ri] = fmaf(v, v, s2v[ri]);
                og = fsigmoid(acc[idx + 1] + vb.y);
                c = comb[idx + 1];
                v = fmaf(og, oa.y - c, c);
                oa.y = v; s1v[ri] += v; s2v[ri] = fmaf(v, v, s2v[ri]);
                *(float2*)(scratch + rr[ri] * SCS + col) = oa;
            }
        }
#pragma unroll
        for (int ri = 0; ri < 4; ++ri) {
#pragma unroll
            for (int o = 1; o < 4; o <<= 1) {
                s1v[ri] += __shfl_xor_sync(0xffffffffu, s1v[ri], o);
                s2v[ri] += __shfl_xor_sync(0xffffffffu, s2v[ri], o);
            }
        }
        if ((l & 3) == 0) {
#pragma unroll
            for (int ri = 0; ri < 4; ++ri)
                *(float2*)(red + rr[ri] * 8 + nhq * 2) = make_float2(s1v[ri], s2v[ri]);
        }
        HBAR();
        if ((l & 3) == 0 && nhq == 0) {
#pragma unroll
            for (int ri = 0; ri < 4; ++ri) {
                float4 qa = *(const float4*)(red + rr[ri] * 8);
                float4 qb = *(const float4*)(red + rr[ri] * 8 + 4);
                float S1 = (qa.x + qa.z) + (qb.x + qb.z);
                float S2 = (qa.y + qa.w) + (qb.y + qb.w);
                float mean = S1 * (1.f / 160.f);
                float var = fmaf(-mean, mean, S2 * (1.f / 160.f));
                *(float2*)(mred + rr[ri] * 2) = make_float2(mean, rsqrtf(var + 1e-3f));
            }
        }
        HBAR();
    }

    /* final LN + coalesced store (rows are half-local: tid>>2) */
    {
        const int row = tid >> 2;
        const int cb2 = (tid & 3) * 40;
        float2 mi = *(const float2*)(mred + row * 2);
        const float mean = mi.x, inv = mi.y;
        const float* sv = scratch + row * SCS + cb2;
        const float4* lg4 = (const float4*)(olng + cb2);
        const float4* lb4 = (const float4*)(olnb + cb2);
        float4* orow = (float4*)(out + (size_t)(m0 + row) * HH + cb2);
#pragma unroll
        for (int q = 0; q < 10; ++q) {
            float4 g4 = lg4[q], bq = lb4[q], o;
            o.x = fmaf((sv[q * 4 + 0] - mean) * inv, g4.x, bq.x);
            o.y = fmaf((sv[q * 4 + 1] - mean) * inv, g4.y, bq.y);
            o.z = fmaf((sv[q * 4 + 2] - mean) * inv, g4.z, bq.z);
            o.w = fmaf((sv[q * 4 + 3] - mean) * inv, g4.w, bq.w);
            orow[q] = o;
        }
    }
#undef HBAR
}

/* --------------------------------- launch --------------------------------- */
extern "C" void kernel_launch(void* const* d_in, const int* in_sizes, int n_in,
                              void* d_out, int out_size) {
    const float* x    = (const float*)d_in[0];
    const float* W1   = (const float*)d_in[1];
    const float* b1   = (const float*)d_in[2];
    const float* W2   = (const float*)d_in[3];
    const float* b2   = (const float*)d_in[4];
    const float* Wg   = (const float*)d_in[5];
    const float* bg   = (const float*)d_in[6];
    const float* lng  = (const float*)d_in[7];
    const float* lnb  = (const float*)d_in[8];
    const float* Ww   = (const float*)d_in[9];
    const float* bw   = (const float*)d_in[10];
    const float* oW1  = (const float*)d_in[11];
    const float* ob1  = (const float*)d_in[12];
    const float* oW2  = (const float*)d_in[13];
    const float* ob2  = (const float*)d_in[14];
    const float* oWg  = (const float*)d_in[15];
    const float* obg  = (const float*)d_in[16];
    const float* olng = (const float*)d_in[17];
    const float* olnb = (const float*)d_in[18];
    float* out = (float*)d_out;

    cudaFuncSetAttribute(fused_mma, cudaFuncAttributeMaxDynamicSharedMemorySize,
                         SMEM_TOTAL);

    pre_kernel<<<BB + 140, 256>>>(W2, oW1, oW2, oWg,
                                  W1, b1, b2, Wg, bg, lng, lnb,
                                  x, Ww, bw, out + (size_t)BB * TT * HH);
    fused_mma<<<(BB * TT) / TM, NTH, SMEM_TOTAL>>>(
        x, ob1, ob2, obg, olng, olnb, out);
}

// round 11
// speedup vs baseline: 1.0696x; 1.0267x over previous
#include <cuda_runtime.h>
#include <cuda_fp16.h>
#include <stdint.h>

#define FF 32
#define HH 160
#define BB 64
#define TT 256
#define TM 64
#define NTH 256
#define EAS 168      /* half stride for A images (>=160, ldmatrix-friendly) */
#define XSTR 33      /* x tile row stride (floats) */

typedef unsigned long long u64;

__device__ float g_weights[BB * FF];
/* B fragments: [t(35)][kt(10)][nt(20)][lane(32)] -> uint2 {b0,b1}
   tile slots: 0..31 = W2[f], 32 = oW1, 33 = oWg, 34 = oW2
   (linear half-chunk index c: uint4 offset c*1600, c = 0..69)                */
__device__ __align__(16) uint2 g_Bfrag[35 * 6400];
/* per-f parameter pack, 1280 floats per f:
   [0,160)=W1  [160,320)=b1  then 5 fragment-major arrays of 192 floats:
   b2@320, Wg@512, bg@704, lng@896, lnb@1088.
   fragment-major: pos = g*48 + tt*12 + j*2 + e for col = g*40 + j*8 + tt*2 + e */
__device__ __align__(16) float g_Par[FF * 1280];

/* ------------------------------ helpers ---------------------------------- */
__device__ __forceinline__ uint32_t smem_u32(const void* p) {
    uint32_t a;
    asm("{ .reg .u64 t; cvta.to.shared.u64 t, %1; cvt.u32.u64 %0, t; }" : "=r"(a) : "l"(p));
    return a;
}
__device__ __forceinline__ uint32_t pack_h2(float a, float b) {
    __half2 h = __floats2half2_rn(a, b);
    return *reinterpret_cast<uint32_t*>(&h);
}
__device__ __forceinline__ u64 packf2(float lo, float hi) {
    u64 r;
    asm("mov.b64 %0, {%1, %2};" : "=l"(r) : "f"(lo), "f"(hi));
    return r;
}
__device__ __forceinline__ void unpackf2(float& lo, float& hi, u64 v) {
    asm("mov.b64 {%0, %1}, %2;" : "=f"(lo), "=f"(hi) : "l"(v));
}
#define FMA2(d, a, b, c) asm("fma.rn.f32x2 %0, %1, %2, %3;" : "=l"(d) : "l"(a), "l"(b), "l"(c))
#define ADD2(d, a, b)    asm("add.rn.f32x2 %0, %1, %2;" : "=l"(d) : "l"(a), "l"(b))
#define MUL2(d, a, b)    asm("mul.rn.f32x2 %0, %1, %2;" : "=l"(d) : "l"(a), "l"(b))

__device__ __forceinline__ u64 fsig2(u64 z, u64 SC1, u64 SC2, u64 SC3, u64 SCH) {
    u64 z2, t;
    MUL2(z2, z, z);
    FMA2(t, z2, SC1, SC2);
    FMA2(t, z2, t, SC3);
    FMA2(t, z, t, SCH);
    return t;
}
__device__ __forceinline__ uint32_t agen2(u64 xg2, u64 w, u64 b,
                                          u64 C120, u64 C24, u64 C6, u64 SCH) {
    u64 z, z2, qq, p;
    FMA2(z, xg2, w, b);
    MUL2(z2, z, z);
    FMA2(qq, z, C120, C24);
    FMA2(qq, z, qq, C6);
    FMA2(qq, z, qq, SCH);
    FMA2(p, z2, qq, z);
    float zl, zh, pl, ph;
    unpackf2(zl, zh, z);
    unpackf2(pl, ph, p);
    float rl = zl > 0.f ? zl : pl;
    float rh = zh > 0.f ? zh : ph;
    return pack_h2(rl, rh);
}
__device__ __forceinline__ float fsigmoid(float z) {
    float z2 = z * z;
    float t = fmaf(z2, 2.0833333e-3f, -2.0833334e-2f);
    t = fmaf(z2, t, 0.25f);
    return fmaf(z, t, 0.5f);
}
__device__ __forceinline__ float felu(float z) {
    float p = fmaf(z, 8.3333333e-3f, 4.1666667e-2f);
    p = fmaf(z, p, 1.6666667e-1f);
    p = fmaf(z, p, 0.5f);
    p = fmaf(z, p, 1.0f);
    p = z * p;
    return z > 0.f ? z : p;
}
__device__ __forceinline__ void mma16816(float* c, uint32_t a0, uint32_t a1,
                                         uint32_t a2, uint32_t a3,
                                         uint32_t b0, uint32_t b1) {
    asm volatile(
        "mma.sync.aligned.m16n8k16.row.col.f32.f16.f16.f32 "
        "{%0,%1,%2,%3}, {%4,%5,%6,%7}, {%8,%9}, {%0,%1,%2,%3};"
        : "+f"(c[0]), "+f"(c[1]), "+f"(c[2]), "+f"(c[3])
        : "r"(a0), "r"(a1), "r"(a2), "r"(a3), "r"(b0), "r"(b1));
}
__device__ __forceinline__ void cp_async16(uint32_t saddr, const void* gptr) {
    asm volatile("cp.async.cg.shared.global [%0], [%1], 16;" :: "r"(saddr), "l"(gptr));
}
#define CP_COMMIT() asm volatile("cp.async.commit_group;" ::: "memory")
#define CP_WAIT0()  asm volatile("cp.async.wait_group 0;" ::: "memory")
#define LDMX4(a0, a1, a2, a3, p)                                                 \
    asm volatile("ldmatrix.sync.aligned.m8n8.x4.shared.b16 {%0,%1,%2,%3}, [%4];" \
                 : "=r"(a0), "=r"(a1), "=r"(a2), "=r"(a3) : "r"(p))

/* gemm chunk: 5 k-tiles, 2 m-tiles per warp, B from smem stage */
__device__ __forceinline__ void gemm_chunk(float* acc, uint32_t ap0, uint32_t ap1,
                                           int h, const uint2* sb) {
#pragma unroll
    for (int kt = 0; kt < 5; ++kt) {
        uint32_t a0, a1, a2, a3, c0, c1, c2, c3;
        LDMX4(a0, a1, a2, a3, ap0 + (h * 5 + kt) * 32);
        LDMX4(c0, c1, c2, c3, ap1 + (h * 5 + kt) * 32);
#pragma unroll
        for (int j = 0; j < 5; ++j) {
            uint2 bv = sb[(kt * 20 + j) * 32];
            mma16816(acc + (j * 2 + 0) * 4, a0, a1, a2, a3, bv.x, bv.y);
            mma16816(acc + (j * 2 + 1) * 4, c0, c1, c2, c3, bv.x, bv.y);
        }
    }
}

/* --------------- kernel 0: merged prep (B fragments + params) + weights --- */
__global__ void pre_kernel(const float* __restrict__ W2,
                           const float* __restrict__ oW1,
                           const float* __restrict__ oW2,
                           const float* __restrict__ oWg,
                           const float* __restrict__ W1,
                           const float* __restrict__ b1,
                           const float* __restrict__ b2,
                           const float* __restrict__ Wg,
                           const float* __restrict__ bg,
                           const float* __restrict__ lng,
                           const float* __restrict__ lnb,
                           const float* __restrict__ x,
                           const float* __restrict__ Ww,
                           const float* __restrict__ bw,
                           float* __restrict__ out_tail) {
    if (blockIdx.x >= BB) {
        int u = blockIdx.x - BB;
        int t = u >> 2, part = u & 3;               /* 35 tiles x 4 parts */
        /* tile slots: 32 = oW1, 33 = oWg, 34 = oW2 (pipeline order) */
        const float* src = (t < 32) ? (W2 + (size_t)t * HH * HH)
                                    : (t == 32 ? oW1 : (t == 33 ? oWg : oW2));
        int base = part * 1600;
        for (int k = threadIdx.x; k < 1600; k += blockDim.x) {
            int idx = base + k;
            int kt = idx / 640;
            int nt = (idx / 32) % 20;
            int l  = idx & 31;
            int k0 = kt * 16 + (l & 3) * 2;
            int n  = nt * 8 + (l >> 2);
            uint2 v;
            v.x = pack_h2(src[k0 * HH + n],       src[(k0 + 1) * HH + n]);
            v.y = pack_h2(src[(k0 + 8) * HH + n], src[(k0 + 9) * HH + n]);
            g_Bfrag[(size_t)t * 6400 + idx] = v;
        }
        if (t < FF && part == 0) {
            const float* srcs[7] = { W1 + t * HH, b1 + t * HH, b2 + t * HH,
                                     Wg + t * HH, bg + t * HH,
                                     lng + t * HH, lnb + t * HH };
            for (int jl = threadIdx.x; jl < 1120; jl += blockDim.x) {
                int a = jl / 160, c = jl - a * 160;
                int p;
                if (a < 2) {
                    p = a * 160 + c;
                } else {
                    int g = c / 40, rem = c - g * 40;
                    int j = rem >> 3, tt = (rem >> 1) & 3, e = rem & 1;
                    p = 320 + (a - 2) * 192 + g * 48 + tt * 12 + j * 2 + e;
                }
                g_Par[t * 1280 + p] = srcs[a][c];
            }
        }
        return;
    }
    int b = blockIdx.x;
    int tid = threadIdx.x;
    int c = tid & 31, g = tid >> 5;
    const float* xb = x + b * (TT * FF);
    float acc = 0.f;
#pragma unroll 4
    for (int r = g; r < TT * FF; r += 8) acc = fmaf(xb[r], Ww[r * FF + c], acc);
    __shared__ float red[8][32];
    red[g][c] = acc;
    __syncthreads();
    if (tid < 32) {
        float s = 0.f;
#pragma unroll
        for (int i = 0; i < 8; ++i) s += red[i][tid];
        s += bw[tid];
        float m = s;
#pragma unroll
        for (int o = 16; o; o >>= 1) m = fmaxf(m, __shfl_xor_sync(0xffffffffu, m, o));
        float e = expf(s - m);
        float se = e;
#pragma unroll
        for (int o = 16; o; o >>= 1) se += __shfl_xor_sync(0xffffffffu, se, o);
        float w = e / se;
        g_weights[b * 32 + tid] = w;
        out_tail[b * 32 + tid] = w;
    }
}

/* ------------------------- kernel 1: fused VSN (HMMA) ---------------------
   SMEM (bytes):
     xs      [0,       8448)   64 x 33 fp32
     eaA     [8448,   29952)   64 x 168 fp16
     red     [29952,  32000)   64 x 8 fp32
     pbuf    [32512,  42752)   2 x 5120 param pack
     Bstage  [42752,  93952)   2 x 25600 cp.async double buffer              */
#define OFF_EAA  8448
#define OFF_RED  29952
#define OFF_PBUF 32512
#define PBF      1280
#define OFF_BST  42752
#define CHKB     25600
#define SMEM_TOTAL 93952

__global__ void __launch_bounds__(NTH, 2)
fused_mma(const float* __restrict__ x,
          const float* __restrict__ ob1, const float* __restrict__ ob2,
          const float* __restrict__ obg,
          const float* __restrict__ olng, const float* __restrict__ olnb,
          float* __restrict__ out) {
    extern __shared__ char smem[];
    float*  xs  = (float*)smem;
    __half* eaA = (__half*)(smem + OFF_EAA);
    float*  red = (float*)(smem + OFF_RED);
    const uint32_t sbase = smem_u32(smem);

    const int tid = threadIdx.x;
    const int l = tid & 31, wid = tid >> 5;
    const int mg = wid >> 2, nhq = wid & 3;
    const int rA = mg * 32 + (l >> 2);
    int rr[4];
    rr[0] = rA; rr[1] = rA + 8; rr[2] = rA + 16; rr[3] = rA + 24;
    const int colbq = nhq * 40;
    const int colt = (l & 3) * 2;
    const int pbase12 = nhq * 48 + (l & 3) * 12;
    const int m0 = blockIdx.x * TM;
    const int bb = blockIdx.x >> 2;

    const int lrow = mg * 32 + (l & 15);
    const int lcol = (l >> 4) * 8;
    const uint32_t aAp0 = sbase + OFF_EAA + (lrow * EAS + lcol) * 2;
    const uint32_t aAp1 = aAp0 + 16 * EAS * 2;
    const int sboff = nhq * 160 + l;

    const int grow = tid >> 2;
    const int gcb = (tid & 3) * 40;

    const u64 SC1  = packf2(2.0833333e-3f, 2.0833333e-3f);
    const u64 SC2  = packf2(-2.0833334e-2f, -2.0833334e-2f);
    const u64 SC3  = packf2(0.25f, 0.25f);
    const u64 SCH  = packf2(0.5f, 0.5f);
    const u64 C120 = packf2(8.3333333e-3f, 8.3333333e-3f);
    const u64 C24  = packf2(4.1666667e-2f, 4.1666667e-2f);
    const u64 C6   = packf2(1.6666667e-1f, 1.6666667e-1f);

#define HBAR() asm volatile("bar.sync %0, 128;" :: "r"(1 + mg) : "memory")

#define AGEN(ff) do {                                                            \
    const float* pbn = (const float*)(smem + OFF_PBUF) + ((ff) & 1) * PBF;       \
    const float xvg = xs[grow * XSTR + (ff)];                                    \
    const u64 xg2 = packf2(xvg, xvg);                                            \
    const u64* W1u = (const u64*)(pbn + gcb);                                    \
    const u64* b1u = (const u64*)(pbn + 160 + gcb);                              \
    uint4* eg = (uint4*)(eaA + grow * EAS + gcb);                                \
    _Pragma("unroll")                                                            \
    for (int q = 0; q < 5; ++q) {                                                \
        uint4 o;                                                                 \
        o.x = agen2(xg2, W1u[4 * q + 0], b1u[4 * q + 0], C120, C24, C6, SCH);    \
        o.y = agen2(xg2, W1u[4 * q + 1], b1u[4 * q + 1], C120, C24, C6, SCH);    \
        o.z = agen2(xg2, W1u[4 * q + 2], b1u[4 * q + 2], C120, C24, C6, SCH);    \
        o.w = agen2(xg2, W1u[4 * q + 3], b1u[4 * q + 3], C120, C24, C6, SCH);    \
        eg[q] = o;                                                               \
    }                                                                            \
} while (0)

/* one pipelined chunk step: wait, publish, prefetch c+1, gemm */
#define CHUNK_STEP(cc, hh, withpar, ff)  do {                                    \
    CP_WAIT0();                                                                  \
    __syncthreads();                                                             \
    if ((cc) + 1 < 70) {                                                         \
        const uint4* gsrc = (const uint4*)g_Bfrag + (size_t)((cc) + 1) * 1600;   \
        const uint32_t dst = sbase + OFF_BST + (((cc) + 1) & 1) * CHKB;          \
        for (int j = tid; j < 1600; j += NTH)                                    \
            cp_async16(dst + j * 16, gsrc + j);                                  \
        if ((withpar) && (ff) + 1 < FF) {                                        \
            const float4* psrc = (const float4*)g_Par + (size_t)((ff) + 1) * 320;\
            const uint32_t pdst = sbase + OFF_PBUF + (((ff) + 1) & 1) * (PBF*4); \
            for (int j = tid; j < 320; j += NTH)                                 \
                cp_async16(pdst + j * 16, psrc + j);                             \
        }                                                                        \
        CP_COMMIT();                                                             \
    }                                                                            \
    const uint2* sb = (const uint2*)(smem + OFF_BST + ((cc) & 1) * CHKB) + sboff;\
    gemm_chunk(acc, aAp0, aAp1, (hh), sb);                                       \
} while (0)

    {
        const float4* xsrc = (const float4*)(x + (size_t)m0 * FF);
        for (int i = tid; i < TM * FF / 4; i += NTH) {
            float4 v = xsrc[i];
            float* d = xs + (i >> 3) * XSTR + ((i & 7) << 2);
            d[0] = v.x; d[1] = v.y; d[2] = v.z; d[3] = v.w;
        }
    }
    /* preload B chunk 0 + params f=0 */
    {
        const uint4* gsrc = (const uint4*)g_Bfrag;
        for (int j = tid; j < 1600; j += NTH)
            cp_async16(sbase + OFF_BST + j * 16, gsrc + j);
        const float4* psrc = (const float4*)g_Par;
        for (int j = tid; j < 320; j += NTH)
            cp_async16(sbase + OFF_PBUF + j * 16, psrc + j);
        CP_COMMIT();
    }
    u64 comb2[20];
#pragma unroll
    for (int i = 0; i < 20; ++i) comb2[i] = 0ull;
    CP_WAIT0();
    __syncthreads();

    float acc[40];
    AGEN(0);

    /* ========================= phase 1: f loop ============================ */
    for (int f = 0; f < FF; ++f) {
        const float* pb = (const float*)(smem + OFF_PBUF) + (f & 1) * PBF;
        float wbf = g_weights[bb * FF + f];

#pragma unroll
        for (int i = 0; i < 40; ++i) acc[i] = 0.f;
        CHUNK_STEP(2 * f,     0, 1, f);
        CHUNK_STEP(2 * f + 1, 1, 0, f);

        /* epilogue pass 1 (packed) */
        u64 xv2[4], nxv2[4], nc02[4], s1p[4], s2p[4];
        float c0v[4];
#pragma unroll
        for (int ri = 0; ri < 4; ++ri) {
            float xv = xs[rr[ri] * XSTR + f];
            float c0 = 0.5f * xv;
            xv2[ri]  = packf2(xv, xv);
            nxv2[ri] = packf2(-xv, -xv);
            nc02[ri] = packf2(-c0, -c0);
            c0v[ri]  = c0;
            s1p[ri] = 0ull; s2p[ri] = 0ull;
        }
        u64 featp[20];
        {
            const u64* pB2 = (const u64*)(pb + 320 + pbase12);
            const u64* pWg = (const u64*)(pb + 512 + pbase12);
            const u64* pBg = (const u64*)(pb + 704 + pbase12);
#pragma unroll
            for (int jv = 0; jv < 5; ++jv) {
                u64 b2p = pB2[jv], wgp = pWg[jv], bgp = pBg[jv];
#pragma unroll
                for (int ri = 0; ri < 4; ++ri) {
                    int idx = (jv * 2 + (ri >> 1)) * 4 + (ri & 1) * 2;
                    u64 ap = packf2(acc[idx], acc[idx + 1]);
                    u64 a2; ADD2(a2, ap, b2p);
                    u64 gz; FMA2(gz, xv2[ri], wgp, bgp);
                    u64 gv = fsig2(gz, SC1, SC2, SC3, SCH);
                    u64 dmx; ADD2(dmx, a2, nxv2[ri]);
                    u64 ft; FMA2(ft, gv, dmx, xv2[ri]);
                    featp[jv * 4 + ri] = ft;
                    u64 d; ADD2(d, ft, nc02[ri]);
                    ADD2(s1p[ri], s1p[ri], d);
                    FMA2(s2p[ri], d, d, s2p[ri]);
                }
            }
        }
        float s1v[4], s2v[4];
#pragma unroll
        for (int ri = 0; ri < 4; ++ri) {
            float a, b2_;
            unpackf2(a, b2_, s1p[ri]); s1v[ri] = a + b2_;
            unpackf2(a, b2_, s2p[ri]); s2v[ri] = a + b2_;
        }
#pragma unroll
        for (int ri = 0; ri < 4; ++ri) {
#pragma unroll
            for (int o = 1; o < 4; o <<= 1) {
                s1v[ri] += __shfl_xor_sync(0xffffffffu, s1v[ri], o);
                s2v[ri] += __shfl_xor_sync(0xffffffffu, s2v[ri], o);
            }
        }
        if ((l & 3) == 0) {
#pragma unroll
            for (int ri = 0; ri < 4; ++ri)
                *(float2*)(red + rr[ri] * 8 + nhq * 2) = make_float2(s1v[ri], s2v[ri]);
        }
        HBAR();

        /* A-gen for f+1 (all half-warps past GEMM(f) ldmatrix; params ready) */
        if (f + 1 < FF) AGEN(f + 1);

        u64 inv2[4], nmi2[4];
#pragma unroll
        for (int ri = 0; ri < 4; ++ri) {
            float4 qa = *(const float4*)(red + rr[ri] * 8);
            float4 qb = *(const float4*)(red + rr[ri] * 8 + 4);
            float S1 = (qa.x + qa.z) + (qb.x + qb.z);
            float S2 = (qa.y + qa.w) + (qb.y + qb.w);
            float dm = S1 * (1.f / 160.f);
            float var = fmaf(-dm, dm, S2 * (1.f / 160.f));
            float inv = rsqrtf(var + 1e-3f);
            float nmi = -(c0v[ri] + dm) * inv;
            inv2[ri] = packf2(inv, inv);
            nmi2[ri] = packf2(nmi, nmi);
        }
        {
            u64 wbf2 = packf2(wbf, wbf);
            const u64* pLg = (const u64*)(pb + 896 + pbase12);
            const u64* pLb = (const u64*)(pb + 1088 + pbase12);
#pragma unroll
            for (int jv = 0; jv < 5; ++jv) {
                u64 lgp = pLg[jv], lbp = pLb[jv];
#pragma unroll
                for (int ri = 0; ri < 4; ++ri) {
                    u64 yt; FMA2(yt, featp[jv * 4 + ri], inv2[ri], nmi2[ri]);
                    u64 y;  FMA2(y, yt, lgp, lbp);
                    FMA2(comb2[jv * 4 + ri], wbf2, y, comb2[jv * 4 + ri]);
                }
            }
        }
        /* no trailing barrier: next CHUNK_STEP's syncthreads publishes eaA */
    }

    /* ========================= phase 2: output MLP ========================
       pipeline continues: chunks 64,65 = oW1; 66,67 = oWg; 68,69 = oW2     */
    HBAR();   /* all half-warps past GEMM(f=31) before eaA overwrite */
#pragma unroll
    for (int jv = 0; jv < 5; ++jv) {
#pragma unroll
        for (int ri = 0; ri < 4; ++ri) {
            float cx, cy;
            unpackf2(cx, cy, comb2[jv * 4 + ri]);
            *(uint32_t*)(eaA + rr[ri] * EAS + colbq + jv * 8 + colt) = pack_h2(cx, cy);
        }
    }
    HBAR();

    /* G1: h1 = elu(comb @ oW1 + ob1) -> registers (fp16 pairs) */
#pragma unroll
    for (int i = 0; i < 40; ++i) acc[i] = 0.f;
    CHUNK_STEP(64, 0, 0, FF);
    CHUNK_STEP(65, 1, 0, FF);
    uint32_t h1p[20];
#pragma unroll
    for (int jv = 0; jv < 5; ++jv)
#pragma unroll
        for (int ri = 0; ri < 4; ++ri) {
            int idx = (jv * 2 + (ri >> 1)) * 4 + (ri & 1) * 2;
            int col = colbq + jv * 8 + colt;
            float2 vb = *(const float2*)(ob1 + col);
            h1p[jv * 4 + ri] =
                pack_h2(felu(acc[idx] + vb.x), felu(acc[idx + 1] + vb.y));
        }

    /* G3: og = sigmoid(comb @ oWg + obg) -> registers (packed fp32) */
#pragma unroll
    for (int i = 0; i < 40; ++i) acc[i] = 0.f;
    CHUNK_STEP(66, 0, 0, FF);
    CHUNK_STEP(67, 1, 0, FF);
    u64 og2[20];
#pragma unroll
    for (int jv = 0; jv < 5; ++jv)
#pragma unroll
        for (int ri = 0; ri < 4; ++ri) {
            int idx = (jv * 2 + (ri >> 1)) * 4 + (ri & 1) * 2;
            int col = colbq + jv * 8 + colt;
            float2 vb = *(const float2*)(obg + col);
            og2[jv * 4 + ri] = packf2(fsigmoid(acc[idx] + vb.x),
                                      fsigmoid(acc[idx + 1] + vb.y));
        }

    /* write h1 -> eaA */
    HBAR();
#pragma unroll
    for (int jv = 0; jv < 5; ++jv)
#pragma unroll
        for (int ri = 0; ri < 4; ++ri)
            *(uint32_t*)(eaA + rr[ri] * EAS + colbq + jv * 8 + colt) = h1p[jv * 4 + ri];
    HBAR();

    /* G2: oa = h1 @ oW2 + ob2 */
#pragma unroll
    for (int i = 0; i < 40; ++i) acc[i] = 0.f;
    CHUNK_STEP(68, 0, 0, FF);
    CHUNK_STEP(69, 1, 0, FF);

    /* combine + final LN + direct fragment-layout store */
    {
        u64 vp[20];
        float s1v[4] = {0.f, 0.f, 0.f, 0.f};
        float s2v[4] = {0.f, 0.f, 0.f, 0.f};
#pragma unroll
        for (int jv = 0; jv < 5; ++jv)
#pragma unroll
            for (int ri = 0; ri < 4; ++ri) {
                int idx = (jv * 2 + (ri >> 1)) * 4 + (ri & 1) * 2;
                int col = colbq + jv * 8 + colt;
                float2 vb = *(const float2*)(ob2 + col);
                float oax = acc[idx] + vb.x;
                float oay = acc[idx + 1] + vb.y;
                float ogx, ogy, cx, cy;
                unpackf2(ogx, ogy, og2[jv * 4 + ri]);
                unpackf2(cx, cy, comb2[jv * 4 + ri]);
                float vx = fmaf(ogx, oax - cx, cx);
                float vy = fmaf(ogy, oay - cy, cy);
                vp[jv * 4 + ri] = packf2(vx, vy);
                s1v[ri] += vx + vy;
                s2v[ri] = fmaf(vx, vx, s2v[ri]);
                s2v[ri] = fmaf(vy, vy, s2v[ri]);
            }
#pragma unroll
        for (int ri = 0; ri < 4; ++ri) {
#pragma unroll
            for (int o = 1; o < 4; o <<= 1) {
                s1v[ri] += __shfl_xor_sync(0xffffffffu, s1v[ri], o);
                s2v[ri] += __shfl_xor_sync(0xffffffffu, s2v[ri], o);
            }
        }
        if ((l & 3) == 0) {
#pragma unroll
            for (int ri = 0; ri < 4; ++ri)
                *(float2*)(red + rr[ri] * 8 + nhq * 2) = make_float2(s1v[ri], s2v[ri]);
        }
        HBAR();
        float meanv[4], invv[4];
#pragma unroll
        for (int ri = 0; ri < 4; ++ri) {
            float4 qa = *(const float4*)(red + rr[ri] * 8);
            float4 qb = *(const float4*)(red + rr[ri] * 8 + 4);
            float S1 = (qa.x + qa.z) + (qb.x + qb.z);
            float S2 = (qa.y + qa.w) + (qb.y + qb.w);
            float mean = S1 * (1.f / 160.f);
            float var = fmaf(-mean, mean, S2 * (1.f / 160.f));
            meanv[ri] = mean;
            invv[ri] = rsqrtf(var + 1e-3f);
        }
#pragma unroll
        for (int jv = 0; jv < 5; ++jv)
#pragma unroll
            for (int ri = 0; ri < 4; ++ri) {
                int col = colbq + jv * 8 + colt;
                float2 lg = *(const float2*)(olng + col);
                float2 lb = *(const float2*)(olnb + col);
                float vx, vy;
                unpackf2(vx, vy, vp[jv * 4 + ri]);
                float2 o;
                o.x = fmaf((vx - meanv[ri]) * invv[ri], lg.x, lb.x);
                o.y = fmaf((vy - meanv[ri]) * invv[ri], lg.y, lb.y);
                *(float2*)(out + (size_t)(m0 + rr[ri]) * HH + col) = o;
            }
    }
#undef HBAR
#undef AGEN
#undef CHUNK_STEP
}

/* --------------------------------- launch --------------------------------- */
extern "C" void kernel_launch(void* const* d_in, const int* in_sizes, int n_in,
                              void* d_out, int out_size) {
    const float* x    = (const float*)d_in[0];
    const float* W1   = (const float*)d_in[1];
    const float* b1   = (const float*)d_in[2];
    const float* W2   = (const float*)d_in[3];
    const float* b2   = (const float*)d_in[4];
    const float* Wg   = (const float*)d_in[5];
    const float* bg   = (const float*)d_in[6];
    const float* lng  = (const float*)d_in[7];
    const float* lnb  = (const float*)d_in[8];
    const float* Ww   = (const float*)d_in[9];
    const float* bw   = (const float*)d_in[10];
    const float* oW1  = (const float*)d_in[11];
    const float* ob1  = (const float*)d_in[12];
    const float* oW2  = (const float*)d_in[13];
    const float* ob2  = (const float*)d_in[14];
    const float* oWg  = (const float*)d_in[15];
    const float* obg  = (const float*)d_in[16];
    const float* olng = (const float*)d_in[17];
    const float* olnb = (const float*)d_in[18];
    float* out = (float*)d_out;

    cudaFuncSetAttribute(fused_mma, cudaFuncAttributeMaxDynamicSharedMemorySize,
                         SMEM_TOTAL);

    pre_kernel<<<BB + 140, 256>>>(W2, oW1, oW2, oWg,
                                  W1, b1, b2, Wg, bg, lng, lnb,
                                  x, Ww, bw, out + (size_t)BB * TT * HH);
    fused_mma<<<(BB * TT) / TM, NTH, SMEM_TOTAL>>>(
        x, ob1, ob2, obg, olng, olnb, out);
}

// round 12
// speedup vs baseline: 1.0844x; 1.0138x over previous
#include <cuda_runtime.h>
#include <cuda_fp16.h>
#include <stdint.h>

#define FF 32
#define HH 160
#define BB 64
#define TT 256
#define TM 64
#define NTH 256
#define EAS 168      /* half stride for A images (>=160, ldmatrix-friendly) */
#define XSTR 33      /* x tile row stride (floats) */

typedef unsigned long long u64;

__device__ float g_weights[BB * FF];
/* B fragments: [t(35)][kt(10)][nt(20)][lane(32)] -> uint2 {b0,b1}
   tile slots: 0..31 = W2[f], 32 = oW1, 33 = oWg, 34 = oW2
   (linear half-chunk index c: uint4 offset c*1600, c = 0..69)                */
__device__ __align__(16) uint2 g_Bfrag[35 * 6400];
/* per-f parameter pack, 1280 floats per f:
   [0,160)=W1  [160,320)=b1  then 5 fragment-major arrays of 192 floats:
   b2@320, Wg@512, bg@704, lng@896, lnb@1088. */
__device__ __align__(16) float g_Par[FF * 1280];

/* ------------------------------ helpers ---------------------------------- */
__device__ __forceinline__ uint32_t smem_u32(const void* p) {
    uint32_t a;
    asm("{ .reg .u64 t; cvta.to.shared.u64 t, %1; cvt.u32.u64 %0, t; }" : "=r"(a) : "l"(p));
    return a;
}
__device__ __forceinline__ uint32_t pack_h2(float a, float b) {
    __half2 h = __floats2half2_rn(a, b);
    return *reinterpret_cast<uint32_t*>(&h);
}
__device__ __forceinline__ u64 packf2(float lo, float hi) {
    u64 r;
    asm("mov.b64 %0, {%1, %2};" : "=l"(r) : "f"(lo), "f"(hi));
    return r;
}
__device__ __forceinline__ void unpackf2(float& lo, float& hi, u64 v) {
    asm("mov.b64 {%0, %1}, %2;" : "=f"(lo), "=f"(hi) : "l"(v));
}
#define FMA2(d, a, b, c) asm("fma.rn.f32x2 %0, %1, %2, %3;" : "=l"(d) : "l"(a), "l"(b), "l"(c))
#define ADD2(d, a, b)    asm("add.rn.f32x2 %0, %1, %2;" : "=l"(d) : "l"(a), "l"(b))
#define MUL2(d, a, b)    asm("mul.rn.f32x2 %0, %1, %2;" : "=l"(d) : "l"(a), "l"(b))

__device__ __forceinline__ u64 fsig2(u64 z, u64 SC1, u64 SC2, u64 SC3, u64 SCH) {
    u64 z2, t;
    MUL2(z2, z, z);
    FMA2(t, z2, SC1, SC2);
    FMA2(t, z2, t, SC3);
    FMA2(t, z, t, SCH);
    return t;
}
__device__ __forceinline__ uint32_t agen2(u64 xg2, u64 w, u64 b,
                                          u64 C120, u64 C24, u64 C6, u64 SCH) {
    u64 z, z2, qq, p;
    FMA2(z, xg2, w, b);
    MUL2(z2, z, z);
    FMA2(qq, z, C120, C24);
    FMA2(qq, z, qq, C6);
    FMA2(qq, z, qq, SCH);
    FMA2(p, z2, qq, z);
    float zl, zh, pl, ph;
    unpackf2(zl, zh, z);
    unpackf2(pl, ph, p);
    float rl = zl > 0.f ? zl : pl;
    float rh = zh > 0.f ? zh : ph;
    return pack_h2(rl, rh);
}
__device__ __forceinline__ float fsigmoid(float z) {
    float z2 = z * z;
    float t = fmaf(z2, 2.0833333e-3f, -2.0833334e-2f);
    t = fmaf(z2, t, 0.25f);
    return fmaf(z, t, 0.5f);
}
__device__ __forceinline__ float felu(float z) {
    float p = fmaf(z, 8.3333333e-3f, 4.1666667e-2f);
    p = fmaf(z, p, 1.6666667e-1f);
    p = fmaf(z, p, 0.5f);
    p = fmaf(z, p, 1.0f);
    p = z * p;
    return z > 0.f ? z : p;
}
__device__ __forceinline__ void mma16816(float* c, uint32_t a0, uint32_t a1,
                                         uint32_t a2, uint32_t a3,
                                         uint32_t b0, uint32_t b1) {
    asm volatile(
        "mma.sync.aligned.m16n8k16.row.col.f32.f16.f16.f32 "
        "{%0,%1,%2,%3}, {%4,%5,%6,%7}, {%8,%9}, {%0,%1,%2,%3};"
        : "+f"(c[0]), "+f"(c[1]), "+f"(c[2]), "+f"(c[3])
        : "r"(a0), "r"(a1), "r"(a2), "r"(a3), "r"(b0), "r"(b1));
}
__device__ __forceinline__ void cp_async16(uint32_t saddr, const void* gptr) {
    asm volatile("cp.async.cg.shared.global [%0], [%1], 16;" :: "r"(saddr), "l"(gptr));
}
#define CP_COMMIT() asm volatile("cp.async.commit_group;" ::: "memory")
#define CP_WAIT0()  asm volatile("cp.async.wait_group 0;" ::: "memory")
#define CP_WAIT1()  asm volatile("cp.async.wait_group 1;" ::: "memory")
#define LDMX4(a0, a1, a2, a3, p)                                                 \
    asm volatile("ldmatrix.sync.aligned.m8n8.x4.shared.b16 {%0,%1,%2,%3}, [%4];" \
                 : "=r"(a0), "=r"(a1), "=r"(a2), "=r"(a3) : "r"(p))

/* gemm chunk: 5 k-tiles, 2 m-tiles per warp, B from smem stage */
__device__ __forceinline__ void gemm_chunk(float* acc, uint32_t ap0, uint32_t ap1,
                                           int h, const uint2* sb) {
#pragma unroll
    for (int kt = 0; kt < 5; ++kt) {
        uint32_t a0, a1, a2, a3, c0, c1, c2, c3;
        LDMX4(a0, a1, a2, a3, ap0 + (h * 5 + kt) * 32);
        LDMX4(c0, c1, c2, c3, ap1 + (h * 5 + kt) * 32);
#pragma unroll
        for (int j = 0; j < 5; ++j) {
            uint2 bv = sb[(kt * 20 + j) * 32];
            mma16816(acc + (j * 2 + 0) * 4, a0, a1, a2, a3, bv.x, bv.y);
            mma16816(acc + (j * 2 + 1) * 4, c0, c1, c2, c3, bv.x, bv.y);
        }
    }
}

/* --------------- kernel 0: merged prep (B fragments + params) + weights --- */
__global__ void pre_kernel(const float* __restrict__ W2,
                           const float* __restrict__ oW1,
                           const float* __restrict__ oW2,
                           const float* __restrict__ oWg,
                           const float* __restrict__ W1,
                           const float* __restrict__ b1,
                           const float* __restrict__ b2,
                           const float* __restrict__ Wg,
                           const float* __restrict__ bg,
                           const float* __restrict__ lng,
                           const float* __restrict__ lnb,
                           const float* __restrict__ x,
                           const float* __restrict__ Ww,
                           const float* __restrict__ bw,
                           float* __restrict__ out_tail) {
    if (blockIdx.x >= BB) {
        int u = blockIdx.x - BB;
        int t = u >> 2, part = u & 3;
        const float* src = (t < 32) ? (W2 + (size_t)t * HH * HH)
                                    : (t == 32 ? oW1 : (t == 33 ? oWg : oW2));
        int base = part * 1600;
        for (int k = threadIdx.x; k < 1600; k += blockDim.x) {
            int idx = base + k;
            int kt = idx / 640;
            int nt = (idx / 32) % 20;
            int l  = idx & 31;
            int k0 = kt * 16 + (l & 3) * 2;
            int n  = nt * 8 + (l >> 2);
            uint2 v;
            v.x = pack_h2(src[k0 * HH + n],       src[(k0 + 1) * HH + n]);
            v.y = pack_h2(src[(k0 + 8) * HH + n], src[(k0 + 9) * HH + n]);
            g_Bfrag[(size_t)t * 6400 + idx] = v;
        }
        if (t < FF && part == 0) {
            const float* srcs[7] = { W1 + t * HH, b1 + t * HH, b2 + t * HH,
                                     Wg + t * HH, bg + t * HH,
                                     lng + t * HH, lnb + t * HH };
            for (int jl = threadIdx.x; jl < 1120; jl += blockDim.x) {
                int a = jl / 160, c = jl - a * 160;
                int p;
                if (a < 2) {
                    p = a * 160 + c;
                } else {
                    int g = c / 40, rem = c - g * 40;
                    int j = rem >> 3, tt = (rem >> 1) & 3, e = rem & 1;
                    p = 320 + (a - 2) * 192 + g * 48 + tt * 12 + j * 2 + e;
                }
                g_Par[t * 1280 + p] = srcs[a][c];
            }
        }
        return;
    }
    int b = blockIdx.x;
    int tid = threadIdx.x;
    int c = tid & 31, g = tid >> 5;
    const float* xb = x + b * (TT * FF);
    float acc = 0.f;
#pragma unroll 4
    for (int r = g; r < TT * FF; r += 8) acc = fmaf(xb[r], Ww[r * FF + c], acc);
    __shared__ float red[8][32];
    red[g][c] = acc;
    __syncthreads();
    if (tid < 32) {
        float s = 0.f;
#pragma unroll
        for (int i = 0; i < 8; ++i) s += red[i][tid];
        s += bw[tid];
        float m = s;
#pragma unroll
        for (int o = 16; o; o >>= 1) m = fmaxf(m, __shfl_xor_sync(0xffffffffu, m, o));
        float e = expf(s - m);
        float se = e;
#pragma unroll
        for (int o = 16; o; o >>= 1) se += __shfl_xor_sync(0xffffffffu, se, o);
        float w = e / se;
        g_weights[b * 32 + tid] = w;
        out_tail[b * 32 + tid] = w;
    }
}

/* ------------------------- kernel 1: fused VSN (HMMA) ---------------------
   SMEM (bytes):
     xs      [0,       8448)   64 x 33 fp32
     eaA     [8448,   29952)   64 x 168 fp16
     red     [29952,  32000)   64 x 8 fp32
     pbuf    [32000,  47360)   3 x 5120 param ring
     Bstage  [47360,  98560)   2 x 25600 cp.async double buffer              */
#define OFF_EAA  8448
#define OFF_RED  29952
#define OFF_PBUF 32000
#define OFF_BST  47360
#define CHKB     25600
#define SMEM_TOTAL 98560

__global__ void __launch_bounds__(NTH, 2)
fused_mma(const float* __restrict__ x,
          const float* __restrict__ ob1, const float* __restrict__ ob2,
          const float* __restrict__ obg,
          const float* __restrict__ olng, const float* __restrict__ olnb,
          float* __restrict__ out) {
    extern __shared__ char smem[];
    float*  xs  = (float*)smem;
    __half* eaA = (__half*)(smem + OFF_EAA);
    float*  red = (float*)(smem + OFF_RED);
    const uint32_t sbase = smem_u32(smem);

    const int tid = threadIdx.x;
    const int l = tid & 31, wid = tid >> 5;
    const int mg = wid >> 2, nhq = wid & 3;
    const int rA = mg * 32 + (l >> 2);
    int rr[4];
    rr[0] = rA; rr[1] = rA + 8; rr[2] = rA + 16; rr[3] = rA + 24;
    const int colbq = nhq * 40;
    const int colt = (l & 3) * 2;
    const int pbase12 = nhq * 48 + (l & 3) * 12;
    const int m0 = blockIdx.x * TM;
    const int bb = blockIdx.x >> 2;

    const int lrow = mg * 32 + (l & 15);
    const int lcol = (l >> 4) * 8;
    const uint32_t aAp0 = sbase + OFF_EAA + (lrow * EAS + lcol) * 2;
    const uint32_t aAp1 = aAp0 + 16 * EAS * 2;
    const int sboff = nhq * 160 + l;

    const int grow = tid >> 2;
    const int gcb = (tid & 3) * 40;

    const u64 SC1  = packf2(2.0833333e-3f, 2.0833333e-3f);
    const u64 SC2  = packf2(-2.0833334e-2f, -2.0833334e-2f);
    const u64 SC3  = packf2(0.25f, 0.25f);
    const u64 SCH  = packf2(0.5f, 0.5f);
    const u64 C120 = packf2(8.3333333e-3f, 8.3333333e-3f);
    const u64 C24  = packf2(4.1666667e-2f, 4.1666667e-2f);
    const u64 C6   = packf2(1.6666667e-1f, 1.6666667e-1f);

    const uint2* buf0 = (const uint2*)(smem + OFF_BST) + sboff;
    const uint2* buf1 = (const uint2*)(smem + OFF_BST + CHKB) + sboff;

#define HBAR() asm volatile("bar.sync %0, 128;" :: "r"(1 + mg) : "memory")

#define PREF_CHUNK(cc, bufi) do {                                                \
    const uint4* gsrc = (const uint4*)g_Bfrag + (size_t)(cc) * 1600;             \
    const uint32_t dst = sbase + OFF_BST + (bufi) * CHKB;                        \
    for (int j = tid; j < 1600; j += NTH)                                        \
        cp_async16(dst + j * 16, gsrc + j);                                      \
} while (0)

#define PREF_PAR(ff) do {                                                        \
    const float4* psrc = (const float4*)g_Par + (size_t)(ff) * 320;              \
    const uint32_t pdst = sbase + OFF_PBUF + ((ff) % 3) * 5120;                  \
    for (int j = tid; j < 320; j += NTH)                                         \
        cp_async16(pdst + j * 16, psrc + j);                                     \
} while (0)

#define AGEN(ff, slot) do {                                                      \
    const float* pbn = (const float*)(smem + OFF_PBUF) + (slot) * 1280;          \
    const float xvg = xs[grow * XSTR + (ff)];                                    \
    const u64 xg2 = packf2(xvg, xvg);                                            \
    const u64* W1u = (const u64*)(pbn + gcb);                                    \
    const u64* b1u = (const u64*)(pbn + 160 + gcb);                              \
    uint4* eg = (uint4*)(eaA + grow * EAS + gcb);                                \
    _Pragma("unroll")                                                            \
    for (int q = 0; q < 5; ++q) {                                                \
        uint4 o;                                                                 \
        o.x = agen2(xg2, W1u[4 * q + 0], b1u[4 * q + 0], C120, C24, C6, SCH);    \
        o.y = agen2(xg2, W1u[4 * q + 1], b1u[4 * q + 1], C120, C24, C6, SCH);    \
        o.z = agen2(xg2, W1u[4 * q + 2], b1u[4 * q + 2], C120, C24, C6, SCH);    \
        o.w = agen2(xg2, W1u[4 * q + 3], b1u[4 * q + 3], C120, C24, C6, SCH);    \
        eg[q] = o;                                                               \
    }                                                                            \
} while (0)

/* full epilogue for feature fe using param slot slotE; consumes acc -> comb2 */
#define EPILOGUE(fe, slotE) do {                                                 \
    const float* pe = (const float*)(smem + OFF_PBUF) + (slotE) * 1280;          \
    float wbf = g_weights[bb * FF + (fe)];                                       \
    u64 xv2[4], nxv2[4], nc02[4], s1p[4], s2p[4];                                \
    float c0v[4];                                                                \
    _Pragma("unroll")                                                            \
    for (int ri = 0; ri < 4; ++ri) {                                             \
        float xv = xs[rr[ri] * XSTR + (fe)];                                     \
        float c0 = 0.5f * xv;                                                    \
        xv2[ri]  = packf2(xv, xv);                                               \
        nxv2[ri] = packf2(-xv, -xv);                                             \
        nc02[ri] = packf2(-c0, -c0);                                             \
        c0v[ri]  = c0;                                                           \
        s1p[ri] = 0ull; s2p[ri] = 0ull;                                          \
    }                                                                            \
    u64 featp[20];                                                               \
    {                                                                            \
        const u64* pB2 = (const u64*)(pe + 320 + pbase12);                       \
        const u64* pWg = (const u64*)(pe + 512 + pbase12);                       \
        const u64* pBg = (const u64*)(pe + 704 + pbase12);                       \
        _Pragma("unroll")                                                        \
        for (int jv = 0; jv < 5; ++jv) {                                         \
            u64 b2p = pB2[jv], wgp = pWg[jv], bgp = pBg[jv];                     \
            _Pragma("unroll")                                                    \
            for (int ri = 0; ri < 4; ++ri) {                                     \
                int idx = (jv * 2 + (ri >> 1)) * 4 + (ri & 1) * 2;               \
                u64 ap = packf2(acc[idx], acc[idx + 1]);                         \
                u64 a2; ADD2(a2, ap, b2p);                                       \
                u64 gz; FMA2(gz, xv2[ri], wgp, bgp);                             \
                u64 gv = fsig2(gz, SC1, SC2, SC3, SCH);                          \
                u64 dmx; ADD2(dmx, a2, nxv2[ri]);                                \
                u64 ft; FMA2(ft, gv, dmx, xv2[ri]);                              \
                featp[jv * 4 + ri] = ft;                                         \
                u64 d; ADD2(d, ft, nc02[ri]);                                    \
                ADD2(s1p[ri], s1p[ri], d);                                       \
                FMA2(s2p[ri], d, d, s2p[ri]);                                    \
            }                                                                    \
        }                                                                        \
    }                                                                            \
    float s1v[4], s2v[4];                                                        \
    _Pragma("unroll")                                                            \
    for (int ri = 0; ri < 4; ++ri) {                                             \
        float a_, b_;                                                            \
        unpackf2(a_, b_, s1p[ri]); s1v[ri] = a_ + b_;                            \
        unpackf2(a_, b_, s2p[ri]); s2v[ri] = a_ + b_;                            \
    }                                                                            \
    _Pragma("unroll")                                                            \
    for (int ri = 0; ri < 4; ++ri) {                                             \
        _Pragma("unroll")                                                        \
        for (int o = 1; o < 4; o <<= 1) {                                        \
            s1v[ri] += __shfl_xor_sync(0xffffffffu, s1v[ri], o);                 \
            s2v[ri] += __shfl_xor_sync(0xffffffffu, s2v[ri], o);                 \
        }                                                                        \
    }                                                                            \
    if ((l & 3) == 0) {                                                          \
        _Pragma("unroll")                                                        \
        for (int ri = 0; ri < 4; ++ri)                                           \
            *(float2*)(red + rr[ri] * 8 + nhq * 2) = make_float2(s1v[ri], s2v[ri]); \
    }                                                                            \
    HBAR();                                                                      \
    u64 inv2[4], nmi2[4];                                                        \
    _Pragma("unroll")                                                            \
    for (int ri = 0; ri < 4; ++ri) {                                             \
        float4 qa = *(const float4*)(red + rr[ri] * 8);                          \
        float4 qb = *(const float4*)(red + rr[ri] * 8 + 4);                      \
        float S1 = (qa.x + qa.z) + (qb.x + qb.z);                                \
        float S2 = (qa.y + qa.w) + (qb.y + qb.w);                                \
        float dm = S1 * (1.f / 160.f);                                           \
        float var = fmaf(-dm, dm, S2 * (1.f / 160.f));                           \
        float inv = rsqrtf(var + 1e-3f);                                         \
        float nmi = -(c0v[ri] + dm) * inv;                                       \
        inv2[ri] = packf2(inv, inv);                                             \
        nmi2[ri] = packf2(nmi, nmi);                                             \
    }                                                                            \
    {                                                                            \
        u64 wbf2 = packf2(wbf, wbf);                                             \
        const u64* pLg = (const u64*)(pe + 896 + pbase12);                       \
        const u64* pLb = (const u64*)(pe + 1088 + pbase12);                      \
        _Pragma("unroll")                                                        \
        for (int jv = 0; jv < 5; ++jv) {                                         \
            u64 lgp = pLg[jv], lbp = pLb[jv];                                    \
            _Pragma("unroll")                                                    \
            for (int ri = 0; ri < 4; ++ri) {                                     \
                u64 yt; FMA2(yt, featp[jv * 4 + ri], inv2[ri], nmi2[ri]);        \
                u64 y;  FMA2(y, yt, lgp, lbp);                                   \
                FMA2(comb2[jv * 4 + ri], wbf2, y, comb2[jv * 4 + ri]);           \
            }                                                                    \
        }                                                                        \
    }                                                                            \
} while (0)

    /* ------------------------------ preamble ------------------------------ */
    {
        const float4* xsrc = (const float4*)(x + (size_t)m0 * FF);
        for (int i = tid; i < TM * FF / 4; i += NTH) {
            float4 v = xsrc[i];
            float* d = xs + (i >> 3) * XSTR + ((i & 7) << 2);
            d[0] = v.x; d[1] = v.y; d[2] = v.z; d[3] = v.w;
        }
    }
    PREF_PAR(0);
    CP_COMMIT();
    u64 comb2[20];
#pragma unroll
    for (int i = 0; i < 20; ++i) comb2[i] = 0ull;
    CP_WAIT0();
    __syncthreads();

    float acc[40];

    /* ========================= phase 1: f loop ============================ */
    for (int f = 0; f < FF; ++f) {
        const int sc = f % 3;
        __syncthreads();   /* all warps past gemms of f-1; buffers + eaA free */
        PREF_CHUNK(2 * f, 0);
        if (f + 1 < FF) PREF_PAR(f + 1);
        CP_COMMIT();
        PREF_CHUNK(2 * f + 1, 1);
        CP_COMMIT();

        AGEN(f, sc);                    /* overlaps the in-flight DMA */
        if (f > 0) EPILOGUE(f - 1, (f - 1) % 3);

#pragma unroll
        for (int i = 0; i < 40; ++i) acc[i] = 0.f;
        CP_WAIT1();
        __syncthreads();               /* buf0 + params(f+1) + eaA published */
        gemm_chunk(acc, aAp0, aAp1, 0, buf0);
        CP_WAIT0();
        __syncthreads();               /* buf1 published */
        gemm_chunk(acc, aAp0, aAp1, 1, buf1);
    }

    /* ========================= phase 2: output MLP ======================== */
    __syncthreads();                   /* all past gemm(63) */
    PREF_CHUNK(64, 0); CP_COMMIT();
    PREF_CHUNK(65, 1); CP_COMMIT();
    EPILOGUE(31, 31 % 3);
    /* comb -> eaA (half-local rows; published by the CP sync below) */
#pragma unroll
    for (int jv = 0; jv < 5; ++jv)
#pragma unroll
        for (int ri = 0; ri < 4; ++ri) {
            float cx, cy;
            unpackf2(cx, cy, comb2[jv * 4 + ri]);
            *(uint32_t*)(eaA + rr[ri] * EAS + colbq + jv * 8 + colt) = pack_h2(cx, cy);
        }

    /* G1: h1 = elu(comb @ oW1 + ob1) */
#pragma unroll
    for (int i = 0; i < 40; ++i) acc[i] = 0.f;
    CP_WAIT1(); __syncthreads(); gemm_chunk(acc, aAp0, aAp1, 0, buf0);
    CP_WAIT0(); __syncthreads(); gemm_chunk(acc, aAp0, aAp1, 1, buf1);
    uint32_t h1p[20];
#pragma unroll
    for (int jv = 0; jv < 5; ++jv)
#pragma unroll
        for (int ri = 0; ri < 4; ++ri) {
            int idx = (jv * 2 + (ri >> 1)) * 4 + (ri & 1) * 2;
            int col = colbq + jv * 8 + colt;
            float2 vb = *(const float2*)(ob1 + col);
            h1p[jv * 4 + ri] =
                pack_h2(felu(acc[idx] + vb.x), felu(acc[idx + 1] + vb.y));
        }

    /* G3: og = sigmoid(comb @ oWg + obg) */
    __syncthreads();                   /* all past G1 gemms */
    PREF_CHUNK(66, 0); CP_COMMIT();
    PREF_CHUNK(67, 1); CP_COMMIT();
#pragma unroll
    for (int i = 0; i < 40; ++i) acc[i] = 0.f;
    CP_WAIT1(); __syncthreads(); gemm_chunk(acc, aAp0, aAp1, 0, buf0);
    CP_WAIT0(); __syncthreads(); gemm_chunk(acc, aAp0, aAp1, 1, buf1);
    u64 og2[20];
#pragma unroll
    for (int jv = 0; jv < 5; ++jv)
#pragma unroll
        for (int ri = 0; ri < 4; ++ri) {
            int idx = (jv * 2 + (ri >> 1)) * 4 + (ri & 1) * 2;
            int col = colbq + jv * 8 + colt;
            float2 vb = *(const float2*)(obg + col);
            og2[jv * 4 + ri] = packf2(fsigmoid(acc[idx] + vb.x),
                                      fsigmoid(acc[idx + 1] + vb.y));
        }

    /* G2: oa = h1 @ oW2 + ob2 */
    __syncthreads();                   /* all past G3 gemms; eaA free */
    PREF_CHUNK(68, 0); CP_COMMIT();
    PREF_CHUNK(69, 1); CP_COMMIT();
#pragma unroll
    for (int jv = 0; jv < 5; ++jv)
#pragma unroll
        for (int ri = 0; ri < 4; ++ri)
            *(uint32_t*)(eaA + rr[ri] * EAS + colbq + jv * 8 + colt) = h1p[jv * 4 + ri];
#pragma unroll
    for (int i = 0; i < 40; ++i) acc[i] = 0.f;
    CP_WAIT1(); __syncthreads(); gemm_chunk(acc, aAp0, aAp1, 0, buf0);
    CP_WAIT0(); __syncthreads(); gemm_chunk(acc, aAp0, aAp1, 1, buf1);

    /* combine + final LN + fragment-layout store */
    {
        u64 vp[20];
        float s1v[4] = {0.f, 0.f, 0.f, 0.f};
        float s2v[4] = {0.f, 0.f, 0.f, 0.f};
#pragma unroll
        for (int jv = 0; jv < 5; ++jv)
#pragma unroll
            for (int ri = 0; ri < 4; ++ri) {
                int idx = (jv * 2 + (ri >> 1)) * 4 + (ri & 1) * 2;
                int col = colbq + jv * 8 + colt;
                float2 vb = *(const float2*)(ob2 + col);
                float oax = acc[idx] + vb.x;
                float oay = acc[idx + 1] + vb.y;
                float ogx, ogy, cx, cy;
                unpackf2(ogx, ogy, og2[jv * 4 + ri]);
                unpackf2(cx, cy, comb2[jv * 4 + ri]);
                float vx = fmaf(ogx, oax - cx, cx);
                float vy = fmaf(ogy, oay - cy, cy);
                vp[jv * 4 + ri] = packf2(vx, vy);
                s1v[ri] += vx + vy;
                s2v[ri] = fmaf(vx, vx, s2v[ri]);
                s2v[ri] = fmaf(vy, vy, s2v[ri]);
            }
#pragma unroll
        for (int ri = 0; ri < 4; ++ri) {
#pragma unroll
            for (int o = 1; o < 4; o <<= 1) {
                s1v[ri] += __shfl_xor_sync(0xffffffffu, s1v[ri], o);
                s2v[ri] += __shfl_xor_sync(0xffffffffu, s2v[ri], o);
            }
        }
        if ((l & 3) == 0) {
#pragma unroll
            for (int ri = 0; ri < 4; ++ri)
                *(float2*)(red + rr[ri] * 8 + nhq * 2) = make_float2(s1v[ri], s2v[ri]);
        }
        HBAR();
        float meanv[4], invv[4];
#pragma unroll
        for (int ri = 0; ri < 4; ++ri) {
            float4 qa = *(const float4*)(red + rr[ri] * 8);
            float4 qb = *(const float4*)(red + rr[ri] * 8 + 4);
            float S1 = (qa.x + qa.z) + (qb.x + qb.z);
            float S2 = (qa.y + qa.w) + (qb.y + qb.w);
            float mean = S1 * (1.f / 160.f);
            float var = fmaf(-mean, mean, S2 * (1.f / 160.f));
            meanv[ri] = mean;
            invv[ri] = rsqrtf(var + 1e-3f);
        }
#pragma unroll
        for (int jv = 0; jv < 5; ++jv)
#pragma unroll
            for (int ri = 0; ri < 4; ++ri) {
                int col = colbq + jv * 8 + colt;
                float2 lg = *(const float2*)(olng + col);
                float2 lb = *(const float2*)(olnb + col);
                float vx, vy;
                unpackf2(vx, vy, vp[jv * 4 + ri]);
                float2 o;
                o.x = fmaf((vx - meanv[ri]) * invv[ri], lg.x, lb.x);
                o.y = fmaf((vy - meanv[ri]) * invv[ri], lg.y, lb.y);
                *(float2*)(out + (size_t)(m0 + rr[ri]) * HH + col) = o;
            }
    }
#undef HBAR
#undef AGEN
#undef EPILOGUE
#undef PREF_CHUNK
#undef PREF_PAR
}

/* --------------------------------- launch --------------------------------- */
extern "C" void kernel_launch(void* const* d_in, const int* in_sizes, int n_in,
                              void* d_out, int out_size) {
    const float* x    = (const float*)d_in[0];
    const float* W1   = (const float*)d_in[1];
    const float* b1   = (const float*)d_in[2];
    const float* W2   = (const float*)d_in[3];
    const float* b2   = (const float*)d_in[4];
    const float* Wg   = (const float*)d_in[5];
    const float* bg   = (const float*)d_in[6];
    const float* lng  = (const float*)d_in[7];
    const float* lnb  = (const float*)d_in[8];
    const float* Ww   = (const float*)d_in[9];
    const float* bw   = (const float*)d_in[10];
    const float* oW1  = (const float*)d_in[11];
    const float* ob1  = (const float*)d_in[12];
    const float* oW2  = (const float*)d_in[13];
    const float* ob2  = (const float*)d_in[14];
    const float* oWg  = (const float*)d_in[15];
    const float* obg  = (const float*)d_in[16];
    const float* olng = (const float*)d_in[17];
    const float* olnb = (const float*)d_in[18];
    float* out = (float*)d_out;

    cudaFuncSetAttribute(fused_mma, cudaFuncAttributeMaxDynamicSharedMemorySize,
                         SMEM_TOTAL);

    pre_kernel<<<BB + 140, 256>>>(W2, oW1, oW2, oWg,
                                  W1, b1, b2, Wg, bg, lng, lnb,
                                  x, Ww, bw, out + (size_t)BB * TT * HH);
    fused_mma<<<(BB * TT) / TM, NTH, SMEM_TOTAL>>>(
        x, ob1, ob2, obg, olng, olnb, out);
}